// round 13
// baseline (speedup 1.0000x reference)
#include <cuda_runtime.h>
#include <cuda_fp16.h>
#include <mma.h>
#include <math.h>

using namespace nvcuda;

// ---------------------------------------------------------------------------
// GATEdgeNet: 2x GATConv (single head) + edge MLP.
//  - all dense GEMMs on tensor cores (fp16 in / fp32 accum), sC aliased on sB
//  - U/V split: x-part precomputed up front, f-part K=64 after GAT2
//  - D = edge_dist @ W_d + b1 precomputed as a wmma GEMM (fused into k_pre)
//  - gatagg: HFMA2 pair accumulation (1/64-scaled weights, flush every 8)
//  - no memset node: g_deg self-restoring (zeroed by k_scan after use)
// ---------------------------------------------------------------------------

constexpr int NN  = 50000;
constexpr int NNP = 50048;
constexpr int NE  = 800000;
constexpr int ET  = 2 * NE + NN;

constexpr int GEMMB = NNP / 128;              // 391
constexpr int DGEMB = NE / 128;               // 6250 (exact)
constexpr int WB    = (NN * 32 + 255) / 256;  // 6250
constexpr int HISTB = 1024;
constexpr int FILLB = 1024;
constexpr int MLPB  = 2048;
// sB (max 64x128 fp16 = 16KB) + sA (128x16 fp16 = 4KB); sC (8KB) aliases [0,8KB)
constexpr int GEMM_SMEM = 64 * 128 * 2 + 128 * 16 * 2;  // 20480

// ---- scratch ----------------------------------------------------------------
__device__ __half g_h1[NNP * 128];
__device__ __half g_f1[NN * 128];
__device__ __half g_h2[NNP * 64];
__device__ __half g_f2[NN * 64];
__device__ __half g_U[NNP * 128];
__device__ __half g_V[NNP * 128];
__device__ __half g_D[NE * 128];
__device__ float g_Uacc[NNP * 128];
__device__ float g_Vacc[NNP * 128];
__device__ float g_s1[NN];
__device__ float g_t1[NN];
__device__ float g_s2[NN];
__device__ float g_t2[NN];
__device__ float g_w2s[128];
__device__ float g_w2d[128];
__device__ int   g_deg[NN];      // zero-init at load; re-zeroed by k_scan
__device__ int   g_rowptr[NN + 1];
__device__ int   g_cursor[NN];
__device__ int   g_adj[ET];

// ---------------------------------------------------------------------------
// Tensor-core GEMM body, dynamic smem. C[128 x BN] tile at block row bx.
// A: fp32/fp16 (lda). B: fp32 K x BN. fp32 accumulate.
// ACC: add Cacc row-block. BIASADD: add bias[col]. OT: __half or float.
// ---------------------------------------------------------------------------
template <int K, int BN, typename AT, bool ACC, bool BIASADD, typename OT>
__device__ __forceinline__ void gemm_wmma(const AT* __restrict__ A, int lda,
                                          const float* __restrict__ B,
                                          OT* __restrict__ C,
                                          const float* __restrict__ Cacc,
                                          const float* __restrict__ bias,
                                          int M, int bx) {
    constexpr int BM = 128;
    constexpr int WN = (BN == 128) ? 4 : 2;
    constexpr int WM = 8 / WN;
    constexpr int TM = BM / WM;
    constexpr int TN = BN / WN;
    constexpr int FM = TM / 16;
    constexpr int FN = TN / 16;

    extern __shared__ unsigned char dynsmem[];
    __half* sB = reinterpret_cast<__half*>(dynsmem);
    __half* sA = reinterpret_cast<__half*>(dynsmem + K * BN * 2);
    float*  sC = reinterpret_cast<float*>(dynsmem);   // aliases sB/sA (dead)

    const int tid  = threadIdx.x;
    const int lane = tid & 31;
    const int wid  = tid >> 5;
    const int wm   = wid / WN, wn = wid % WN;
    const int bm   = bx * BM;

    for (int i = tid; i < K * BN; i += 256)
        sB[i] = __float2half(B[i]);

    wmma::fragment<wmma::accumulator, 16, 16, 16, float> acc[FM][FN];
    #pragma unroll
    for (int i = 0; i < FM; i++)
        #pragma unroll
        for (int j = 0; j < FN; j++)
            wmma::fill_fragment(acc[i][j], 0.f);

    #pragma unroll
    for (int k0 = 0; k0 < K; k0 += 16) {
        __syncthreads();
        #pragma unroll
        for (int i = tid; i < BM * 8; i += 256) {
            int r = i >> 3, cp = i & 7;
            int row = bm + r;
            if (row >= M) row = M - 1;
            __half2 hv;
            if (sizeof(AT) == 4) {
                float2 f = *reinterpret_cast<const float2*>(
                    reinterpret_cast<const float*>(A) + (size_t)row * lda + k0 + cp * 2);
                hv = __floats2half2_rn(f.x, f.y);
            } else {
                hv = *reinterpret_cast<const __half2*>(
                    reinterpret_cast<const __half*>(A) + (size_t)row * lda + k0 + cp * 2);
            }
            reinterpret_cast<__half2*>(sA)[i] = hv;
        }
        __syncthreads();

        wmma::fragment<wmma::matrix_a, 16, 16, 16, __half, wmma::row_major> af[FM];
        #pragma unroll
        for (int i = 0; i < FM; i++)
            wmma::load_matrix_sync(af[i], sA + (wm * TM + i * 16) * 16, 16);
        wmma::fragment<wmma::matrix_b, 16, 16, 16, __half, wmma::row_major> bf[FN];
        #pragma unroll
        for (int j = 0; j < FN; j++)
            wmma::load_matrix_sync(bf[j], sB + k0 * BN + wn * TN + j * 16, BN);
        #pragma unroll
        for (int i = 0; i < FM; i++)
            #pragma unroll
            for (int j = 0; j < FN; j++)
                wmma::mma_sync(acc[i][j], af[i], bf[j], acc[i][j]);
    }
    __syncthreads();   // sA/sB dead; sC (aliased) now safe to write

    float* scw = sC + wid * 256;
    const int r  = lane >> 1;
    const int c0 = (lane & 1) * 8;
    #pragma unroll
    for (int i = 0; i < FM; i++)
        #pragma unroll
        for (int j = 0; j < FN; j++) {
            wmma::store_matrix_sync(scw, acc[i][j], 16, wmma::mem_row_major);
            __syncwarp();
            float4 p0 = *reinterpret_cast<float4*>(scw + r * 16 + c0);
            float4 p1 = *reinterpret_cast<float4*>(scw + r * 16 + c0 + 4);
            const int row = bm + wm * TM + i * 16 + r;
            const int col = wn * TN + j * 16 + c0;
            if (ACC) {
                float4 a0 = *reinterpret_cast<const float4*>(
                    Cacc + (size_t)row * BN + col);
                float4 a1 = *reinterpret_cast<const float4*>(
                    Cacc + (size_t)row * BN + col + 4);
                p0.x += a0.x; p0.y += a0.y; p0.z += a0.z; p0.w += a0.w;
                p1.x += a1.x; p1.y += a1.y; p1.z += a1.z; p1.w += a1.w;
            }
            if (BIASADD) {
                float4 b0 = *reinterpret_cast<const float4*>(bias + col);
                float4 b1v = *reinterpret_cast<const float4*>(bias + col + 4);
                p0.x += b0.x; p0.y += b0.y; p0.z += b0.z; p0.w += b0.w;
                p1.x += b1v.x; p1.y += b1v.y; p1.z += b1v.z; p1.w += b1v.w;
            }
            if (sizeof(OT) == 2) {
                __half2 h[4];
                h[0] = __floats2half2_rn(p0.x, p0.y);
                h[1] = __floats2half2_rn(p0.z, p0.w);
                h[2] = __floats2half2_rn(p1.x, p1.y);
                h[3] = __floats2half2_rn(p1.z, p1.w);
                *reinterpret_cast<uint4*>(
                    reinterpret_cast<__half*>(C) + (size_t)row * BN + col) =
                    *reinterpret_cast<uint4*>(h);
            } else {
                float* cp = reinterpret_cast<float*>(C) + (size_t)row * BN + col;
                *reinterpret_cast<float4*>(cp)     = p0;
                *reinterpret_cast<float4*>(cp + 4) = p1;
            }
            __syncwarp();
        }
}

// ---------------------------------------------------------------------------
// Fused: gemm1 (x@Wg1 -> h1) | Ux | Vx | D (ed@Wd + b1) | hist
// ---------------------------------------------------------------------------
__global__ void __launch_bounds__(256)
k_pre(const float* __restrict__ x, const int* __restrict__ ei,
      const float* __restrict__ ed,
      const float* __restrict__ Wg1, const float* __restrict__ Wm1,
      const float* __restrict__ bm1,
      __half* __restrict__ h1, float* __restrict__ Uacc,
      float* __restrict__ Vacc, __half* __restrict__ D) {
    const int bx = blockIdx.x;
    if (bx < GEMMB) {
        gemm_wmma<64, 128, float, false, false, __half>(
            x, 64, Wg1, h1, nullptr, nullptr, NN, bx);
    } else if (bx < 2 * GEMMB) {
        gemm_wmma<64, 128, float, false, false, float>(
            x, 64, Wm1, Uacc, nullptr, nullptr, NN, bx - GEMMB);
    } else if (bx < 3 * GEMMB) {
        gemm_wmma<64, 128, float, false, false, float>(
            x, 64, Wm1 + 128 * 128, Vacc, nullptr, nullptr, NN, bx - 2 * GEMMB);
    } else if (bx < 3 * GEMMB + DGEMB) {
        gemm_wmma<16, 128, float, false, true, __half>(
            ed, 16, Wm1 + 256 * 128, D, nullptr, bm1, NE, bx - 3 * GEMMB);
    } else {
        const int b = bx - 3 * GEMMB - DGEMB;
        for (int t = b * 256 + threadIdx.x; t < NE; t += HISTB * 256) {
            int2 rc = *reinterpret_cast<const int2*>(ei + 2 * t);
            atomicAdd(&g_deg[rc.x], 1);
            atomicAdd(&g_deg[rc.y], 1);
        }
    }
}

// ---------------------------------------------------------------------------
// Single-block scan over (deg + 1) + w~2 projection vectors.
// Re-zeroes g_deg after reading (keeps graph replays deterministic,
// replaces the memset node; __device__ globals start zeroed at load).
// ---------------------------------------------------------------------------
__global__ void __launch_bounds__(1024)
k_scan(const float* __restrict__ Wg2, const float* __restrict__ a2s,
       const float* __restrict__ a2d) {
    constexpr int CH = (NN + 1023) / 1024;
    __shared__ int wsum[32];
    const int tid  = threadIdx.x;
    const int lane = tid & 31;
    const int wid  = tid >> 5;
    const int base = tid * CH;

    if (tid < 128) {
        float ws = 0.f, wd = 0.f;
        const float* r = Wg2 + tid * 64;
        #pragma unroll 8
        for (int j = 0; j < 64; j++) {
            float v = r[j];
            ws = fmaf(v, __ldg(a2s + j), ws);
            wd = fmaf(v, __ldg(a2d + j), wd);
        }
        g_w2s[tid] = ws;
        g_w2d[tid] = wd;
    }

    int vals[CH];
    int s = 0;
    #pragma unroll
    for (int k = 0; k < CH; k++) {
        int i = base + k;
        int v = 0;
        if (i < NN) {
            v = g_deg[i] + 1;
            g_deg[i] = 0;          // restore for next replay
        }
        vals[k] = v;
        s += v;
    }
    int x = s;
    #pragma unroll
    for (int off = 1; off < 32; off <<= 1) {
        int y = __shfl_up_sync(0xffffffffu, x, off);
        if (lane >= off) x += y;
    }
    if (lane == 31) wsum[wid] = x;
    __syncthreads();
    if (wid == 0) {
        int w = wsum[lane];
        #pragma unroll
        for (int off = 1; off < 32; off <<= 1) {
            int y = __shfl_up_sync(0xffffffffu, w, off);
            if (lane >= off) w += y;
        }
        wsum[lane] = w;
    }
    __syncthreads();

    int run = x - s + (wid ? wsum[wid - 1] : 0);
    if (tid == 0) g_rowptr[0] = 0;
    #pragma unroll
    for (int k = 0; k < CH; k++) {
        int i = base + k;
        if (i < NN) {
            g_cursor[i] = run;
            run += vals[k];
            g_rowptr[i + 1] = run;
        }
    }
}

// ---------------------------------------------------------------------------
// Fused: CSR fill (single pass + self loops) | rowdots1 (h1 fp16)
// ---------------------------------------------------------------------------
__global__ void __launch_bounds__(256)
k_fill_rd(const int* __restrict__ ei,
          const float* __restrict__ a1s, const float* __restrict__ a1d) {
    const int bx = blockIdx.x;
    if (bx < FILLB) {
        const int total = NE + NN;
        for (int t = bx * 256 + threadIdx.x; t < total; t += FILLB * 256) {
            if (t < NE) {
                int2 rc = *reinterpret_cast<const int2*>(ei + 2 * t);
                int p1 = atomicAdd(&g_cursor[rc.y], 1);
                g_adj[p1] = rc.x;
                int p2 = atomicAdd(&g_cursor[rc.x], 1);
                g_adj[p2] = rc.y;
            } else {
                int n = t - NE;
                int p = atomicAdd(&g_cursor[n], 1);
                g_adj[p] = n;
            }
        }
    } else {
        const int w = ((bx - FILLB) * 256 + threadIdx.x) >> 5;
        const int lane = threadIdx.x & 31;
        if (w >= NN) return;
        const __half2* hr = reinterpret_cast<const __half2*>(g_h1 + (size_t)w * 128);
        float ds = 0.f, dt = 0.f;
        #pragma unroll
        for (int p = lane; p < 64; p += 32) {
            float2 v = __half22float2(hr[p]);
            ds = fmaf(v.x, __ldg(a1s + 2 * p), fmaf(v.y, __ldg(a1s + 2 * p + 1), ds));
            dt = fmaf(v.x, __ldg(a1d + 2 * p), fmaf(v.y, __ldg(a1d + 2 * p + 1), dt));
        }
        #pragma unroll
        for (int o = 16; o; o >>= 1) {
            ds += __shfl_xor_sync(0xffffffffu, ds, o);
            dt += __shfl_xor_sync(0xffffffffu, dt, o);
        }
        if (lane == 0) { g_s1[w] = ds; g_t1[w] = dt; }
    }
}

// ---------------------------------------------------------------------------
// GAT aggregation: warp per dst node, per-lane columns, HFMA2 accumulation.
// Weights broadcast as packed half2 (scaled by 1/64 against fp16 overflow);
// fp16 partials flushed to fp32 every 8 edges. Final scale-back via inv*64.
// ---------------------------------------------------------------------------
template <int C>
__global__ void k_gatagg(const __half* __restrict__ h,
                         const float* __restrict__ s,
                         const float* __restrict__ t,
                         const float* __restrict__ bias,
                         __half* __restrict__ outh) {
    constexpr int NH = C / 64;                 // half2 accumulators per lane
    int w = (blockIdx.x * blockDim.x + threadIdx.x) >> 5;
    int lane = threadIdx.x & 31;
    if (w >= NN) return;

    const int beg = g_rowptr[w];
    const int end = g_rowptr[w + 1];
    const float tn = t[w];
    const __half2 HZ = __floats2half2_rn(0.f, 0.f);

    float denom = 0.f;
    float facc[2 * NH];
    __half2 hacc[NH];
    #pragma unroll
    for (int q = 0; q < 2 * NH; q++) facc[q] = 0.f;
    #pragma unroll
    for (int q = 0; q < NH; q++) hacc[q] = HZ;

    int j0 = beg;
    for (; j0 + 32 <= end; j0 += 32) {          // full chunks
        int sj = g_adj[j0 + lane];
        float e = s[sj] + tn;
        e = (e >= 0.f) ? e : 0.2f * e;
        float wv = __expf(e);
        denom += wv;
        float wvs = wv * 0.015625f;             // 1/64 overflow guard
        __half2 wv2 = __floats2half2_rn(wvs, wvs);
        unsigned wv2u = *reinterpret_cast<unsigned*>(&wv2);
        #pragma unroll
        for (int k = 0; k < 32; k++) {
            unsigned wk2u = __shfl_sync(0xffffffffu, wv2u, k);
            int      sk   = __shfl_sync(0xffffffffu, sj, k);
            __half2 wk2 = *reinterpret_cast<__half2*>(&wk2u);
            if (C == 128) {
                uint2 raw = *reinterpret_cast<const uint2*>(
                    h + (size_t)sk * C + lane * 4);
                hacc[0] = __hfma2(*reinterpret_cast<__half2*>(&raw.x), wk2, hacc[0]);
                hacc[NH - 1] = __hfma2(*reinterpret_cast<__half2*>(&raw.y), wk2,
                                       hacc[NH - 1]);
            } else {
                __half2 raw = *reinterpret_cast<const __half2*>(
                    h + (size_t)sk * C + lane * 2);
                hacc[0] = __hfma2(raw, wk2, hacc[0]);
            }
            if ((k & 7) == 7) {
                #pragma unroll
                for (int q = 0; q < NH; q++) {
                    float2 f = __half22float2(hacc[q]);
                    facc[2 * q]     += f.x;
                    facc[2 * q + 1] += f.y;
                    hacc[q] = HZ;
                }
            }
        }
    }
    if (j0 < end) {                              // remainder
        int j = j0 + lane;
        float wv = 0.f;
        int sj = 0;
        if (j < end) {
            sj = g_adj[j];
            float e = s[sj] + tn;
            e = (e >= 0.f) ? e : 0.2f * e;
            wv = __expf(e);
        }
        denom += wv;
        float wvs = wv * 0.015625f;
        __half2 wv2 = __floats2half2_rn(wvs, wvs);
        unsigned wv2u = *reinterpret_cast<unsigned*>(&wv2);
        int cnt = end - j0;
        for (int k = 0; k < cnt; k++) {
            unsigned wk2u = __shfl_sync(0xffffffffu, wv2u, k);
            int      sk   = __shfl_sync(0xffffffffu, sj, k);
            __half2 wk2 = *reinterpret_cast<__half2*>(&wk2u);
            if (C == 128) {
                uint2 raw = *reinterpret_cast<const uint2*>(
                    h + (size_t)sk * C + lane * 4);
                hacc[0] = __hfma2(*reinterpret_cast<__half2*>(&raw.x), wk2, hacc[0]);
                hacc[NH - 1] = __hfma2(*reinterpret_cast<__half2*>(&raw.y), wk2,
                                       hacc[NH - 1]);
            } else {
                __half2 raw = *reinterpret_cast<const __half2*>(
                    h + (size_t)sk * C + lane * 2);
                hacc[0] = __hfma2(raw, wk2, hacc[0]);
            }
            if ((k & 7) == 7) {
                #pragma unroll
                for (int q = 0; q < NH; q++) {
                    float2 f = __half22float2(hacc[q]);
                    facc[2 * q]     += f.x;
                    facc[2 * q + 1] += f.y;
                    hacc[q] = HZ;
                }
            }
        }
        #pragma unroll
        for (int q = 0; q < NH; q++) {           // final flush
            float2 f = __half22float2(hacc[q]);
            facc[2 * q]     += f.x;
            facc[2 * q + 1] += f.y;
        }
    }
    #pragma unroll
    for (int o = 16; o; o >>= 1)
        denom += __shfl_xor_sync(0xffffffffu, denom, o);

    const float inv = 64.f / (denom + 1e-16f);   // undo 1/64 weight scale
    if (C == 128) {
        __half2 hh[2];
        hh[0] = __floats2half2_rn(
            fmaxf(facc[0] * inv + __ldg(bias + lane * 4 + 0), 0.f),
            fmaxf(facc[1] * inv + __ldg(bias + lane * 4 + 1), 0.f));
        hh[1] = __floats2half2_rn(
            fmaxf(facc[2] * inv + __ldg(bias + lane * 4 + 2), 0.f),
            fmaxf(facc[3] * inv + __ldg(bias + lane * 4 + 3), 0.f));
        *reinterpret_cast<uint2*>(outh + (size_t)w * C + lane * 4) =
            *reinterpret_cast<uint2*>(hh);
    } else {
        __half2 hh = __floats2half2_rn(
            fmaxf(facc[0] * inv + __ldg(bias + lane * 2 + 0), 0.f),
            fmaxf(facc[1] * inv + __ldg(bias + lane * 2 + 1), 0.f));
        *reinterpret_cast<__half2*>(outh + (size_t)w * C + lane * 2) = hh;
    }
}

// ---------------------------------------------------------------------------
// Fused: gemm2 (f1 fp16 @ Wg2 -> h2 fp16) | rowdots2 (f1 fp16, w~2)
// ---------------------------------------------------------------------------
__global__ void __launch_bounds__(256)
k_sgemm2_rd(const __half* __restrict__ f1, const float* __restrict__ Wg2,
            __half* __restrict__ h2) {
    const int bx = blockIdx.x;
    if (bx < GEMMB) {
        gemm_wmma<128, 64, __half, false, false, __half>(
            f1, 128, Wg2, h2, nullptr, nullptr, NN, bx);
    } else {
        const int w = ((bx - GEMMB) * 256 + threadIdx.x) >> 5;
        const int lane = threadIdx.x & 31;
        if (w >= NN) return;
        uint2 raw = *reinterpret_cast<const uint2*>(f1 + (size_t)w * 128 + lane * 4);
        float2 v01 = __half22float2(*reinterpret_cast<__half2*>(&raw.x));
        float2 v23 = __half22float2(*reinterpret_cast<__half2*>(&raw.y));
        float4 ws = *reinterpret_cast<const float4*>(g_w2s + lane * 4);
        float4 wd = *reinterpret_cast<const float4*>(g_w2d + lane * 4);
        float ds = v01.x * ws.x + v01.y * ws.y + v23.x * ws.z + v23.y * ws.w;
        float dt = v01.x * wd.x + v01.y * wd.y + v23.x * wd.z + v23.y * wd.w;
        #pragma unroll
        for (int o = 16; o; o >>= 1) {
            ds += __shfl_xor_sync(0xffffffffu, ds, o);
            dt += __shfl_xor_sync(0xffffffffu, dt, o);
        }
        if (lane == 0) { g_s2[w] = ds; g_t2[w] = dt; }
    }
}

// ---------------------------------------------------------------------------
// Fused U & V f-part GEMMs with accumulate from precomputed x-parts.
// ---------------------------------------------------------------------------
__global__ void __launch_bounds__(256)
k_uvf(const __half* __restrict__ f2, const float* __restrict__ Wm1,
      const float* __restrict__ Uacc, const float* __restrict__ Vacc,
      __half* __restrict__ U, __half* __restrict__ V) {
    if (blockIdx.y == 0)
        gemm_wmma<64, 128, __half, true, false, __half>(
            f2, 64, Wm1 + 64 * 128, U, Uacc, nullptr, NN, blockIdx.x);
    else
        gemm_wmma<64, 128, __half, true, false, __half>(
            f2, 64, Wm1 + 192 * 128, V, Vacc, nullptr, NN, blockIdx.x);
}

// ---------------------------------------------------------------------------
// Edge MLP: a = relu_h2(U[row] + V[col] + D[e]); out = sigmoid(a.W2 + b2)
// ---------------------------------------------------------------------------
__global__ void __launch_bounds__(256)
k_edgemlp(const int* __restrict__ ei,
          const __half* __restrict__ U, const __half* __restrict__ V,
          const __half* __restrict__ D,
          const float* __restrict__ Wm2, const float* __restrict__ b2,
          float* __restrict__ out) {
    const int tid = threadIdx.x;
    const int lane = tid & 31;

    float4 w2r = *reinterpret_cast<const float4*>(Wm2 + lane * 4);
    const float b2v = __ldg(b2);
    const __half2 z2 = __floats2half2_rn(0.f, 0.f);

    const int gw  = (blockIdx.x * 256 + tid) >> 5;
    const int nw  = MLPB * 8;
    const int epw = (NE + nw - 1) / nw;
    const int e0  = gw * epw;
    const int e1  = (e0 + epw < NE) ? e0 + epw : NE;

    #pragma unroll 2
    for (int e = e0; e < e1; e++) {
        int2 rc = *reinterpret_cast<const int2*>(ei + 2 * e);

        uint2 ur = *reinterpret_cast<const uint2*>(U + (size_t)rc.x * 128 + lane * 4);
        uint2 vr = *reinterpret_cast<const uint2*>(V + (size_t)rc.y * 128 + lane * 4);
        uint2 dr = *reinterpret_cast<const uint2*>(D + (size_t)e * 128 + lane * 4);

        __half2 u0 = *reinterpret_cast<__half2*>(&ur.x);
        __half2 u1 = *reinterpret_cast<__half2*>(&ur.y);
        __half2 v0 = *reinterpret_cast<__half2*>(&vr.x);
        __half2 v1 = *reinterpret_cast<__half2*>(&vr.y);
        __half2 d0 = *reinterpret_cast<__half2*>(&dr.x);
        __half2 d1 = *reinterpret_cast<__half2*>(&dr.y);

        __half2 s0 = __hmax2(__hadd2(__hadd2(u0, v0), d0), z2);
        __half2 s1 = __hmax2(__hadd2(__hadd2(u1, v1), d1), z2);

        float2 f0 = __half22float2(s0);
        float2 f1 = __half22float2(s1);
        float p = f0.x * w2r.x + f0.y * w2r.y + f1.x * w2r.z + f1.y * w2r.w;
        #pragma unroll
        for (int o = 16; o; o >>= 1)
            p += __shfl_xor_sync(0xffffffffu, p, o);

        if (lane == 0)
            out[e] = 1.f / (1.f + __expf(-(p + b2v)));
    }
}

// ---------------------------------------------------------------------------
extern "C" void kernel_launch(void* const* d_in, const int* in_sizes, int n_in,
                              void* d_out, int out_size) {
    const float* x    = (const float*)d_in[0];
    const int*   ei   = (const int*)  d_in[1];
    const float* ed   = (const float*)d_in[2];
    const float* Wg1  = (const float*)d_in[3];
    const float* a1s  = (const float*)d_in[4];
    const float* a1d  = (const float*)d_in[5];
    const float* bg1  = (const float*)d_in[6];
    const float* Wg2  = (const float*)d_in[7];
    const float* a2s  = (const float*)d_in[8];
    const float* a2d  = (const float*)d_in[9];
    const float* bg2  = (const float*)d_in[10];
    const float* Wm1  = (const float*)d_in[11];
    const float* bm1  = (const float*)d_in[12];
    const float* Wm2  = (const float*)d_in[13];
    const float* bm2  = (const float*)d_in[14];
    float* out = (float*)d_out;

    __half *h1, *f1, *h2, *f2, *U, *V, *D;
    float *Uacc, *Vacc, *s1, *t1, *s2, *t2;
    cudaGetSymbolAddress((void**)&h1, g_h1);
    cudaGetSymbolAddress((void**)&f1, g_f1);
    cudaGetSymbolAddress((void**)&h2, g_h2);
    cudaGetSymbolAddress((void**)&f2, g_f2);
    cudaGetSymbolAddress((void**)&U,  g_U);
    cudaGetSymbolAddress((void**)&V,  g_V);
    cudaGetSymbolAddress((void**)&D,  g_D);
    cudaGetSymbolAddress((void**)&Uacc, g_Uacc);
    cudaGetSymbolAddress((void**)&Vacc, g_Vacc);
    cudaGetSymbolAddress((void**)&s1, g_s1);
    cudaGetSymbolAddress((void**)&t1, g_t1);
    cudaGetSymbolAddress((void**)&s2, g_s2);
    cudaGetSymbolAddress((void**)&t2, g_t2);

    // gemm1 | Ux | Vx | D | hist   (g_deg arrives zeroed; k_scan restores it)
    k_pre<<<3 * GEMMB + DGEMB + HISTB, 256, GEMM_SMEM>>>(
        x, ei, ed, Wg1, Wm1, bm1, h1, Uacc, Vacc, D);
    // scan (+self loops) + w~2 + g_deg reset
    k_scan<<<1, 1024>>>(Wg2, a2s, a2d);
    // fill | rowdots1
    k_fill_rd<<<FILLB + WB, 256>>>(ei, a1s, a1d);
    // GAT aggregate 1 -> f1 (fp16)
    k_gatagg<128><<<WB, 256>>>(h1, s1, t1, bg1, f1);
    // gemm2 | rowdots2
    k_sgemm2_rd<<<GEMMB + WB, 256, GEMM_SMEM>>>(f1, Wg2, h2);
    // GAT aggregate 2 -> f2 (fp16)
    k_gatagg<64><<<WB, 256>>>(h2, s2, t2, bg2, f2);
    // U/V f-part GEMMs + accumulate x-parts
    k_uvf<<<dim3(GEMMB, 2), 256, GEMM_SMEM>>>(f2, Wm1, Uacc, Vacc, U, V);
    // edge MLP (gather + add + relu + dot)
    k_edgemlp<<<MLPB, 256>>>(ei, U, V, D, Wm2, bm2, out);
}

// round 14
// speedup vs baseline: 1.0123x; 1.0123x over previous
#include <cuda_runtime.h>
#include <cuda_fp16.h>
#include <mma.h>
#include <math.h>

using namespace nvcuda;

// ---------------------------------------------------------------------------
// GATEdgeNet: 2x GATConv (single head) + edge MLP.
//  - all dense GEMMs on tensor cores (fp16 in / fp32 accum), sC aliased on sB
//  - U/V split: x-part precomputed up front, f-part K=64 after GAT2
//  - D = edge_dist @ W_d + b1 precomputed as a wmma GEMM (fused into k_pre)
//  - gatagg: R12-proven fp32-FMA body (32 regs, occ 84% — do not touch)
//  - no memset node: g_deg self-restoring (zeroed by k_scan after use)
// ---------------------------------------------------------------------------

constexpr int NN  = 50000;
constexpr int NNP = 50048;
constexpr int NE  = 800000;
constexpr int ET  = 2 * NE + NN;

constexpr int GEMMB = NNP / 128;              // 391
constexpr int DGEMB = NE / 128;               // 6250 (exact)
constexpr int WB    = (NN * 32 + 255) / 256;  // 6250
constexpr int HISTB = 1024;
constexpr int FILLB = 1024;
constexpr int MLPB  = 2048;
// sB (max 64x128 fp16 = 16KB) + sA (128x16 fp16 = 4KB); sC (8KB) aliases [0,8KB)
constexpr int GEMM_SMEM = 64 * 128 * 2 + 128 * 16 * 2;  // 20480

// ---- scratch ----------------------------------------------------------------
__device__ __half g_h1[NNP * 128];
__device__ __half g_f1[NN * 128];
__device__ __half g_h2[NNP * 64];
__device__ __half g_f2[NN * 64];
__device__ __half g_U[NNP * 128];
__device__ __half g_V[NNP * 128];
__device__ __half g_D[NE * 128];
__device__ float g_Uacc[NNP * 128];
__device__ float g_Vacc[NNP * 128];
__device__ float g_s1[NN];
__device__ float g_t1[NN];
__device__ float g_s2[NN];
__device__ float g_t2[NN];
__device__ float g_w2s[128];
__device__ float g_w2d[128];
__device__ int   g_deg[NN];      // zero-init at load; re-zeroed by k_scan
__device__ int   g_rowptr[NN + 1];
__device__ int   g_cursor[NN];
__device__ int   g_adj[ET];

// ---------------------------------------------------------------------------
// Tensor-core GEMM body, dynamic smem. C[128 x BN] tile at block row bx.
// A: fp32/fp16 (lda). B: fp32 K x BN. fp32 accumulate.
// ACC: add Cacc row-block. BIASADD: add bias[col]. OT: __half or float.
// ---------------------------------------------------------------------------
template <int K, int BN, typename AT, bool ACC, bool BIASADD, typename OT>
__device__ __forceinline__ void gemm_wmma(const AT* __restrict__ A, int lda,
                                          const float* __restrict__ B,
                                          OT* __restrict__ C,
                                          const float* __restrict__ Cacc,
                                          const float* __restrict__ bias,
                                          int M, int bx) {
    constexpr int BM = 128;
    constexpr int WN = (BN == 128) ? 4 : 2;
    constexpr int WM = 8 / WN;
    constexpr int TM = BM / WM;
    constexpr int TN = BN / WN;
    constexpr int FM = TM / 16;
    constexpr int FN = TN / 16;

    extern __shared__ unsigned char dynsmem[];
    __half* sB = reinterpret_cast<__half*>(dynsmem);
    __half* sA = reinterpret_cast<__half*>(dynsmem + K * BN * 2);
    float*  sC = reinterpret_cast<float*>(dynsmem);   // aliases sB/sA (dead)

    const int tid  = threadIdx.x;
    const int lane = tid & 31;
    const int wid  = tid >> 5;
    const int wm   = wid / WN, wn = wid % WN;
    const int bm   = bx * BM;

    for (int i = tid; i < K * BN; i += 256)
        sB[i] = __float2half(B[i]);

    wmma::fragment<wmma::accumulator, 16, 16, 16, float> acc[FM][FN];
    #pragma unroll
    for (int i = 0; i < FM; i++)
        #pragma unroll
        for (int j = 0; j < FN; j++)
            wmma::fill_fragment(acc[i][j], 0.f);

    #pragma unroll
    for (int k0 = 0; k0 < K; k0 += 16) {
        __syncthreads();
        #pragma unroll
        for (int i = tid; i < BM * 8; i += 256) {
            int r = i >> 3, cp = i & 7;
            int row = bm + r;
            if (row >= M) row = M - 1;
            __half2 hv;
            if (sizeof(AT) == 4) {
                float2 f = *reinterpret_cast<const float2*>(
                    reinterpret_cast<const float*>(A) + (size_t)row * lda + k0 + cp * 2);
                hv = __floats2half2_rn(f.x, f.y);
            } else {
                hv = *reinterpret_cast<const __half2*>(
                    reinterpret_cast<const __half*>(A) + (size_t)row * lda + k0 + cp * 2);
            }
            reinterpret_cast<__half2*>(sA)[i] = hv;
        }
        __syncthreads();

        wmma::fragment<wmma::matrix_a, 16, 16, 16, __half, wmma::row_major> af[FM];
        #pragma unroll
        for (int i = 0; i < FM; i++)
            wmma::load_matrix_sync(af[i], sA + (wm * TM + i * 16) * 16, 16);
        wmma::fragment<wmma::matrix_b, 16, 16, 16, __half, wmma::row_major> bf[FN];
        #pragma unroll
        for (int j = 0; j < FN; j++)
            wmma::load_matrix_sync(bf[j], sB + k0 * BN + wn * TN + j * 16, BN);
        #pragma unroll
        for (int i = 0; i < FM; i++)
            #pragma unroll
            for (int j = 0; j < FN; j++)
                wmma::mma_sync(acc[i][j], af[i], bf[j], acc[i][j]);
    }
    __syncthreads();   // sA/sB dead; sC (aliased) now safe to write

    float* scw = sC + wid * 256;
    const int r  = lane >> 1;
    const int c0 = (lane & 1) * 8;
    #pragma unroll
    for (int i = 0; i < FM; i++)
        #pragma unroll
        for (int j = 0; j < FN; j++) {
            wmma::store_matrix_sync(scw, acc[i][j], 16, wmma::mem_row_major);
            __syncwarp();
            float4 p0 = *reinterpret_cast<float4*>(scw + r * 16 + c0);
            float4 p1 = *reinterpret_cast<float4*>(scw + r * 16 + c0 + 4);
            const int row = bm + wm * TM + i * 16 + r;
            const int col = wn * TN + j * 16 + c0;
            if (ACC) {
                float4 a0 = *reinterpret_cast<const float4*>(
                    Cacc + (size_t)row * BN + col);
                float4 a1 = *reinterpret_cast<const float4*>(
                    Cacc + (size_t)row * BN + col + 4);
                p0.x += a0.x; p0.y += a0.y; p0.z += a0.z; p0.w += a0.w;
                p1.x += a1.x; p1.y += a1.y; p1.z += a1.z; p1.w += a1.w;
            }
            if (BIASADD) {
                float4 b0 = *reinterpret_cast<const float4*>(bias + col);
                float4 b1v = *reinterpret_cast<const float4*>(bias + col + 4);
                p0.x += b0.x; p0.y += b0.y; p0.z += b0.z; p0.w += b0.w;
                p1.x += b1v.x; p1.y += b1v.y; p1.z += b1v.z; p1.w += b1v.w;
            }
            if (sizeof(OT) == 2) {
                __half2 h[4];
                h[0] = __floats2half2_rn(p0.x, p0.y);
                h[1] = __floats2half2_rn(p0.z, p0.w);
                h[2] = __floats2half2_rn(p1.x, p1.y);
                h[3] = __floats2half2_rn(p1.z, p1.w);
                *reinterpret_cast<uint4*>(
                    reinterpret_cast<__half*>(C) + (size_t)row * BN + col) =
                    *reinterpret_cast<uint4*>(h);
            } else {
                float* cp = reinterpret_cast<float*>(C) + (size_t)row * BN + col;
                *reinterpret_cast<float4*>(cp)     = p0;
                *reinterpret_cast<float4*>(cp + 4) = p1;
            }
            __syncwarp();
        }
}

// ---------------------------------------------------------------------------
// Fused: gemm1 (x@Wg1 -> h1) | Ux | Vx | D (ed@Wd + b1) | hist
// ---------------------------------------------------------------------------
__global__ void __launch_bounds__(256)
k_pre(const float* __restrict__ x, const int* __restrict__ ei,
      const float* __restrict__ ed,
      const float* __restrict__ Wg1, const float* __restrict__ Wm1,
      const float* __restrict__ bm1,
      __half* __restrict__ h1, float* __restrict__ Uacc,
      float* __restrict__ Vacc, __half* __restrict__ D) {
    const int bx = blockIdx.x;
    if (bx < GEMMB) {
        gemm_wmma<64, 128, float, false, false, __half>(
            x, 64, Wg1, h1, nullptr, nullptr, NN, bx);
    } else if (bx < 2 * GEMMB) {
        gemm_wmma<64, 128, float, false, false, float>(
            x, 64, Wm1, Uacc, nullptr, nullptr, NN, bx - GEMMB);
    } else if (bx < 3 * GEMMB) {
        gemm_wmma<64, 128, float, false, false, float>(
            x, 64, Wm1 + 128 * 128, Vacc, nullptr, nullptr, NN, bx - 2 * GEMMB);
    } else if (bx < 3 * GEMMB + DGEMB) {
        gemm_wmma<16, 128, float, false, true, __half>(
            ed, 16, Wm1 + 256 * 128, D, nullptr, bm1, NE, bx - 3 * GEMMB);
    } else {
        const int b = bx - 3 * GEMMB - DGEMB;
        for (int t = b * 256 + threadIdx.x; t < NE; t += HISTB * 256) {
            int2 rc = *reinterpret_cast<const int2*>(ei + 2 * t);
            atomicAdd(&g_deg[rc.x], 1);
            atomicAdd(&g_deg[rc.y], 1);
        }
    }
}

// ---------------------------------------------------------------------------
// Single-block scan over (deg + 1) + w~2 projection vectors.
// Re-zeroes g_deg after reading (replaces the memset node).
// ---------------------------------------------------------------------------
__global__ void __launch_bounds__(1024)
k_scan(const float* __restrict__ Wg2, const float* __restrict__ a2s,
       const float* __restrict__ a2d) {
    constexpr int CH = (NN + 1023) / 1024;
    __shared__ int wsum[32];
    const int tid  = threadIdx.x;
    const int lane = tid & 31;
    const int wid  = tid >> 5;
    const int base = tid * CH;

    if (tid < 128) {
        float ws = 0.f, wd = 0.f;
        const float* r = Wg2 + tid * 64;
        #pragma unroll 8
        for (int j = 0; j < 64; j++) {
            float v = r[j];
            ws = fmaf(v, __ldg(a2s + j), ws);
            wd = fmaf(v, __ldg(a2d + j), wd);
        }
        g_w2s[tid] = ws;
        g_w2d[tid] = wd;
    }

    int vals[CH];
    int s = 0;
    #pragma unroll
    for (int k = 0; k < CH; k++) {
        int i = base + k;
        int v = 0;
        if (i < NN) {
            v = g_deg[i] + 1;
            g_deg[i] = 0;          // restore for next replay
        }
        vals[k] = v;
        s += v;
    }
    int x = s;
    #pragma unroll
    for (int off = 1; off < 32; off <<= 1) {
        int y = __shfl_up_sync(0xffffffffu, x, off);
        if (lane >= off) x += y;
    }
    if (lane == 31) wsum[wid] = x;
    __syncthreads();
    if (wid == 0) {
        int w = wsum[lane];
        #pragma unroll
        for (int off = 1; off < 32; off <<= 1) {
            int y = __shfl_up_sync(0xffffffffu, w, off);
            if (lane >= off) w += y;
        }
        wsum[lane] = w;
    }
    __syncthreads();

    int run = x - s + (wid ? wsum[wid - 1] : 0);
    if (tid == 0) g_rowptr[0] = 0;
    #pragma unroll
    for (int k = 0; k < CH; k++) {
        int i = base + k;
        if (i < NN) {
            g_cursor[i] = run;
            run += vals[k];
            g_rowptr[i + 1] = run;
        }
    }
}

// ---------------------------------------------------------------------------
// Fused: CSR fill (single pass + self loops) | rowdots1 (h1 fp16)
// ---------------------------------------------------------------------------
__global__ void __launch_bounds__(256)
k_fill_rd(const int* __restrict__ ei,
          const float* __restrict__ a1s, const float* __restrict__ a1d) {
    const int bx = blockIdx.x;
    if (bx < FILLB) {
        const int total = NE + NN;
        for (int t = bx * 256 + threadIdx.x; t < total; t += FILLB * 256) {
            if (t < NE) {
                int2 rc = *reinterpret_cast<const int2*>(ei + 2 * t);
                int p1 = atomicAdd(&g_cursor[rc.y], 1);
                g_adj[p1] = rc.x;
                int p2 = atomicAdd(&g_cursor[rc.x], 1);
                g_adj[p2] = rc.y;
            } else {
                int n = t - NE;
                int p = atomicAdd(&g_cursor[n], 1);
                g_adj[p] = n;
            }
        }
    } else {
        const int w = ((bx - FILLB) * 256 + threadIdx.x) >> 5;
        const int lane = threadIdx.x & 31;
        if (w >= NN) return;
        const __half2* hr = reinterpret_cast<const __half2*>(g_h1 + (size_t)w * 128);
        float ds = 0.f, dt = 0.f;
        #pragma unroll
        for (int p = lane; p < 64; p += 32) {
            float2 v = __half22float2(hr[p]);
            ds = fmaf(v.x, __ldg(a1s + 2 * p), fmaf(v.y, __ldg(a1s + 2 * p + 1), ds));
            dt = fmaf(v.x, __ldg(a1d + 2 * p), fmaf(v.y, __ldg(a1d + 2 * p + 1), dt));
        }
        #pragma unroll
        for (int o = 16; o; o >>= 1) {
            ds += __shfl_xor_sync(0xffffffffu, ds, o);
            dt += __shfl_xor_sync(0xffffffffu, dt, o);
        }
        if (lane == 0) { g_s1[w] = ds; g_t1[w] = dt; }
    }
}

// ---------------------------------------------------------------------------
// GAT aggregation (R12-proven shape — DO NOT MODIFY): warp per dst node,
// per-lane columns (CPL = C/32), 32-edge unrolled chunks, fp32 FMA, fp16 out.
// ---------------------------------------------------------------------------
template <int C>
__device__ __forceinline__ void gat_accum(const __half* __restrict__ h,
                                          int sk, float wk, int lane,
                                          float* acc) {
    if (C == 128) {
        uint2 raw = *reinterpret_cast<const uint2*>(h + (size_t)sk * C + lane * 4);
        float2 lo = __half22float2(*reinterpret_cast<__half2*>(&raw.x));
        float2 hi = __half22float2(*reinterpret_cast<__half2*>(&raw.y));
        acc[0] = fmaf(wk, lo.x, acc[0]);
        acc[1] = fmaf(wk, lo.y, acc[1]);
        acc[2] = fmaf(wk, hi.x, acc[2]);
        acc[3] = fmaf(wk, hi.y, acc[3]);
    } else {
        __half2 raw = *reinterpret_cast<const __half2*>(h + (size_t)sk * C + lane * 2);
        float2 v = __half22float2(raw);
        acc[0] = fmaf(wk, v.x, acc[0]);
        acc[1] = fmaf(wk, v.y, acc[1]);
    }
}

template <int C>
__global__ void k_gatagg(const __half* __restrict__ h,
                         const float* __restrict__ s,
                         const float* __restrict__ t,
                         const float* __restrict__ bias,
                         __half* __restrict__ outh) {
    constexpr int CPL = C / 32;
    int w = (blockIdx.x * blockDim.x + threadIdx.x) >> 5;
    int lane = threadIdx.x & 31;
    if (w >= NN) return;

    const int beg = g_rowptr[w];
    const int end = g_rowptr[w + 1];
    const float tn = t[w];

    float denom = 0.f;
    float acc[CPL];
    #pragma unroll
    for (int q = 0; q < CPL; q++) acc[q] = 0.f;

    int j0 = beg;
    for (; j0 + 32 <= end; j0 += 32) {          // full chunks
        int sj = g_adj[j0 + lane];
        float e = s[sj] + tn;
        e = (e >= 0.f) ? e : 0.2f * e;
        float wv = __expf(e);
        denom += wv;
        #pragma unroll
        for (int k = 0; k < 32; k++) {
            float wk = __shfl_sync(0xffffffffu, wv, k);
            int   sk = __shfl_sync(0xffffffffu, sj, k);
            gat_accum<C>(h, sk, wk, lane, acc);
        }
    }
    if (j0 < end) {                              // remainder
        int j = j0 + lane;
        float wv = 0.f;
        int sj = 0;
        if (j < end) {
            sj = g_adj[j];
            float e = s[sj] + tn;
            e = (e >= 0.f) ? e : 0.2f * e;
            wv = __expf(e);
        }
        denom += wv;
        int cnt = end - j0;
        for (int k = 0; k < cnt; k++) {
            float wk = __shfl_sync(0xffffffffu, wv, k);
            int   sk = __shfl_sync(0xffffffffu, sj, k);
            gat_accum<C>(h, sk, wk, lane, acc);
        }
    }
    #pragma unroll
    for (int o = 16; o; o >>= 1)
        denom += __shfl_xor_sync(0xffffffffu, denom, o);

    const float inv = 1.f / (denom + 1e-16f);
    if (CPL == 4) {
        __half2 hh[2];
        hh[0] = __floats2half2_rn(
            fmaxf(acc[0] * inv + __ldg(bias + lane * 4 + 0), 0.f),
            fmaxf(acc[1] * inv + __ldg(bias + lane * 4 + 1), 0.f));
        hh[1] = __floats2half2_rn(
            fmaxf(acc[2] * inv + __ldg(bias + lane * 4 + 2), 0.f),
            fmaxf(acc[3] * inv + __ldg(bias + lane * 4 + 3), 0.f));
        *reinterpret_cast<uint2*>(outh + (size_t)w * C + lane * 4) =
            *reinterpret_cast<uint2*>(hh);
    } else {
        __half2 hh = __floats2half2_rn(
            fmaxf(acc[0] * inv + __ldg(bias + lane * 2 + 0), 0.f),
            fmaxf(acc[1] * inv + __ldg(bias + lane * 2 + 1), 0.f));
        *reinterpret_cast<__half2*>(outh + (size_t)w * C + lane * 2) = hh;
    }
}

// ---------------------------------------------------------------------------
// Fused: gemm2 (f1 fp16 @ Wg2 -> h2 fp16) | rowdots2 (f1 fp16, w~2)
// ---------------------------------------------------------------------------
__global__ void __launch_bounds__(256)
k_sgemm2_rd(const __half* __restrict__ f1, const float* __restrict__ Wg2,
            __half* __restrict__ h2) {
    const int bx = blockIdx.x;
    if (bx < GEMMB) {
        gemm_wmma<128, 64, __half, false, false, __half>(
            f1, 128, Wg2, h2, nullptr, nullptr, NN, bx);
    } else {
        const int w = ((bx - GEMMB) * 256 + threadIdx.x) >> 5;
        const int lane = threadIdx.x & 31;
        if (w >= NN) return;
        uint2 raw = *reinterpret_cast<const uint2*>(f1 + (size_t)w * 128 + lane * 4);
        float2 v01 = __half22float2(*reinterpret_cast<__half2*>(&raw.x));
        float2 v23 = __half22float2(*reinterpret_cast<__half2*>(&raw.y));
        float4 ws = *reinterpret_cast<const float4*>(g_w2s + lane * 4);
        float4 wd = *reinterpret_cast<const float4*>(g_w2d + lane * 4);
        float ds = v01.x * ws.x + v01.y * ws.y + v23.x * ws.z + v23.y * ws.w;
        float dt = v01.x * wd.x + v01.y * wd.y + v23.x * wd.z + v23.y * wd.w;
        #pragma unroll
        for (int o = 16; o; o >>= 1) {
            ds += __shfl_xor_sync(0xffffffffu, ds, o);
            dt += __shfl_xor_sync(0xffffffffu, dt, o);
        }
        if (lane == 0) { g_s2[w] = ds; g_t2[w] = dt; }
    }
}

// ---------------------------------------------------------------------------
// Fused U & V f-part GEMMs with accumulate from precomputed x-parts.
// ---------------------------------------------------------------------------
__global__ void __launch_bounds__(256)
k_uvf(const __half* __restrict__ f2, const float* __restrict__ Wm1,
      const float* __restrict__ Uacc, const float* __restrict__ Vacc,
      __half* __restrict__ U, __half* __restrict__ V) {
    if (blockIdx.y == 0)
        gemm_wmma<64, 128, __half, true, false, __half>(
            f2, 64, Wm1 + 64 * 128, U, Uacc, nullptr, NN, blockIdx.x);
    else
        gemm_wmma<64, 128, __half, true, false, __half>(
            f2, 64, Wm1 + 192 * 128, V, Vacc, nullptr, NN, blockIdx.x);
}

// ---------------------------------------------------------------------------
// Edge MLP: a = relu_h2(U[row] + V[col] + D[e]); out = sigmoid(a.W2 + b2)
// ---------------------------------------------------------------------------
__global__ void __launch_bounds__(256)
k_edgemlp(const int* __restrict__ ei,
          const __half* __restrict__ U, const __half* __restrict__ V,
          const __half* __restrict__ D,
          const float* __restrict__ Wm2, const float* __restrict__ b2,
          float* __restrict__ out) {
    const int tid = threadIdx.x;
    const int lane = tid & 31;

    float4 w2r = *reinterpret_cast<const float4*>(Wm2 + lane * 4);
    const float b2v = __ldg(b2);
    const __half2 z2 = __floats2half2_rn(0.f, 0.f);

    const int gw  = (blockIdx.x * 256 + tid) >> 5;
    const int nw  = MLPB * 8;
    const int epw = (NE + nw - 1) / nw;
    const int e0  = gw * epw;
    const int e1  = (e0 + epw < NE) ? e0 + epw : NE;

    #pragma unroll 2
    for (int e = e0; e < e1; e++) {
        int2 rc = *reinterpret_cast<const int2*>(ei + 2 * e);

        uint2 ur = *reinterpret_cast<const uint2*>(U + (size_t)rc.x * 128 + lane * 4);
        uint2 vr = *reinterpret_cast<const uint2*>(V + (size_t)rc.y * 128 + lane * 4);
        uint2 dr = *reinterpret_cast<const uint2*>(D + (size_t)e * 128 + lane * 4);

        __half2 u0 = *reinterpret_cast<__half2*>(&ur.x);
        __half2 u1 = *reinterpret_cast<__half2*>(&ur.y);
        __half2 v0 = *reinterpret_cast<__half2*>(&vr.x);
        __half2 v1 = *reinterpret_cast<__half2*>(&vr.y);
        __half2 d0 = *reinterpret_cast<__half2*>(&dr.x);
        __half2 d1 = *reinterpret_cast<__half2*>(&dr.y);

        __half2 s0 = __hmax2(__hadd2(__hadd2(u0, v0), d0), z2);
        __half2 s1 = __hmax2(__hadd2(__hadd2(u1, v1), d1), z2);

        float2 f0 = __half22float2(s0);
        float2 f1 = __half22float2(s1);
        float p = f0.x * w2r.x + f0.y * w2r.y + f1.x * w2r.z + f1.y * w2r.w;
        #pragma unroll
        for (int o = 16; o; o >>= 1)
            p += __shfl_xor_sync(0xffffffffu, p, o);

        if (lane == 0)
            out[e] = 1.f / (1.f + __expf(-(p + b2v)));
    }
}

// ---------------------------------------------------------------------------
extern "C" void kernel_launch(void* const* d_in, const int* in_sizes, int n_in,
                              void* d_out, int out_size) {
    const float* x    = (const float*)d_in[0];
    const int*   ei   = (const int*)  d_in[1];
    const float* ed   = (const float*)d_in[2];
    const float* Wg1  = (const float*)d_in[3];
    const float* a1s  = (const float*)d_in[4];
    const float* a1d  = (const float*)d_in[5];
    const float* bg1  = (const float*)d_in[6];
    const float* Wg2  = (const float*)d_in[7];
    const float* a2s  = (const float*)d_in[8];
    const float* a2d  = (const float*)d_in[9];
    const float* bg2  = (const float*)d_in[10];
    const float* Wm1  = (const float*)d_in[11];
    const float* bm1  = (const float*)d_in[12];
    const float* Wm2  = (const float*)d_in[13];
    const float* bm2  = (const float*)d_in[14];
    float* out = (float*)d_out;

    __half *h1, *f1, *h2, *f2, *U, *V, *D;
    float *Uacc, *Vacc, *s1, *t1, *s2, *t2;
    cudaGetSymbolAddress((void**)&h1, g_h1);
    cudaGetSymbolAddress((void**)&f1, g_f1);
    cudaGetSymbolAddress((void**)&h2, g_h2);
    cudaGetSymbolAddress((void**)&f2, g_f2);
    cudaGetSymbolAddress((void**)&U,  g_U);
    cudaGetSymbolAddress((void**)&V,  g_V);
    cudaGetSymbolAddress((void**)&D,  g_D);
    cudaGetSymbolAddress((void**)&Uacc, g_Uacc);
    cudaGetSymbolAddress((void**)&Vacc, g_Vacc);
    cudaGetSymbolAddress((void**)&s1, g_s1);
    cudaGetSymbolAddress((void**)&t1, g_t1);
    cudaGetSymbolAddress((void**)&s2, g_s2);
    cudaGetSymbolAddress((void**)&t2, g_t2);

    // gemm1 | Ux | Vx | D | hist   (g_deg arrives zeroed; k_scan restores it)
    k_pre<<<3 * GEMMB + DGEMB + HISTB, 256, GEMM_SMEM>>>(
        x, ei, ed, Wg1, Wm1, bm1, h1, Uacc, Vacc, D);
    // scan (+self loops) + w~2 + g_deg reset
    k_scan<<<1, 1024>>>(Wg2, a2s, a2d);
    // fill | rowdots1
    k_fill_rd<<<FILLB + WB, 256>>>(ei, a1s, a1d);
    // GAT aggregate 1 -> f1 (fp16)
    k_gatagg<128><<<WB, 256>>>(h1, s1, t1, bg1, f1);
    // gemm2 | rowdots2
    k_sgemm2_rd<<<GEMMB + WB, 256, GEMM_SMEM>>>(f1, Wg2, h2);
    // GAT aggregate 2 -> f2 (fp16)
    k_gatagg<64><<<WB, 256>>>(h2, s2, t2, bg2, f2);
    // U/V f-part GEMMs + accumulate x-parts
    k_uvf<<<dim3(GEMMB, 2), 256, GEMM_SMEM>>>(f2, Wm1, Uacc, Vacc, U, V);
    // edge MLP (gather + add + relu + dot)
    k_edgemlp<<<MLPB, 256>>>(ei, U, V, D, Wm2, bm2, out);
}

// round 15
// speedup vs baseline: 1.0658x; 1.0528x over previous
#include <cuda_runtime.h>
#include <cuda_fp16.h>
#include <mma.h>
#include <math.h>

using namespace nvcuda;

// ---------------------------------------------------------------------------
// GATEdgeNet: 2x GATConv (single head) + edge MLP.
// Exactly the R12 best-measured configuration, with ONE change:
// the D = edge_dist @ W_d + b1 GEMM is fused INTO k_edgemlp (per-block wmma
// into smem), eliminating the 410 MB D write+read round-trip through DRAM.
// ---------------------------------------------------------------------------

constexpr int NN  = 50000;
constexpr int NNP = 50048;
constexpr int NE  = 800000;
constexpr int ET  = 2 * NE + NN;

constexpr int GEMMB = NNP / 128;              // 391
constexpr int EDGEB = NE / 128;               // 6250 (exact)
constexpr int WB    = (NN * 32 + 255) / 256;  // 6250
constexpr int HISTB = 1024;
constexpr int FILLB = 1024;
constexpr int GEMM_SMEM = 64 * 128 * 2 + 128 * 16 * 2 + 8 * 256 * 4;  // 28672
// edgemlp: sB 16x128 fp16 (4KB) + sA 128x16 fp16 (4KB) + sD 128x128 fp16 (32KB)
//          + sC 8x256 fp32 (8KB) = 48KB (default dynamic-smem limit)
constexpr int EMLP_SMEM = 16 * 128 * 2 + 128 * 16 * 2 + 128 * 128 * 2 + 8 * 256 * 4;

// ---- scratch ----------------------------------------------------------------
__device__ __half g_h1[NNP * 128];
__device__ __half g_f1[NN * 128];
__device__ __half g_h2[NNP * 64];
__device__ __half g_f2[NN * 64];
__device__ __half g_U[NNP * 128];
__device__ __half g_V[NNP * 128];
__device__ float g_Uacc[NNP * 128];
__device__ float g_Vacc[NNP * 128];
__device__ float g_s1[NN];
__device__ float g_t1[NN];
__device__ float g_s2[NN];
__device__ float g_t2[NN];
__device__ float g_w2s[128];
__device__ float g_w2d[128];
__device__ int   g_deg[NN];
__device__ int   g_rowptr[NN + 1];
__device__ int   g_cursor[NN];
__device__ int   g_adj[ET];

// ---------------------------------------------------------------------------
// Tensor-core GEMM body (R12-proven), dynamic smem, separate sC region.
// ---------------------------------------------------------------------------
template <int K, int BN, typename AT, bool ACC, typename OT>
__device__ __forceinline__ void gemm_wmma(const AT* __restrict__ A, int lda,
                                          const float* __restrict__ B,
                                          OT* __restrict__ C,
                                          const float* __restrict__ Cacc,
                                          int M, int bx) {
    constexpr int BM = 128;
    constexpr int WN = (BN == 128) ? 4 : 2;
    constexpr int WM = 8 / WN;
    constexpr int TM = BM / WM;
    constexpr int TN = BN / WN;
    constexpr int FM = TM / 16;
    constexpr int FN = TN / 16;

    extern __shared__ unsigned char dynsmem[];
    __half* sB = reinterpret_cast<__half*>(dynsmem);
    __half* sA = reinterpret_cast<__half*>(dynsmem + K * BN * 2);
    float*  sC = reinterpret_cast<float*>(dynsmem + K * BN * 2 + BM * 16 * 2);

    const int tid  = threadIdx.x;
    const int lane = tid & 31;
    const int wid  = tid >> 5;
    const int wm   = wid / WN, wn = wid % WN;
    const int bm   = bx * BM;

    for (int i = tid; i < K * BN; i += 256)
        sB[i] = __float2half(B[i]);

    wmma::fragment<wmma::accumulator, 16, 16, 16, float> acc[FM][FN];
    #pragma unroll
    for (int i = 0; i < FM; i++)
        #pragma unroll
        for (int j = 0; j < FN; j++)
            wmma::fill_fragment(acc[i][j], 0.f);

    #pragma unroll
    for (int k0 = 0; k0 < K; k0 += 16) {
        __syncthreads();
        #pragma unroll
        for (int i = tid; i < BM * 8; i += 256) {
            int r = i >> 3, cp = i & 7;
            int row = bm + r;
            if (row >= M) row = M - 1;
            __half2 hv;
            if (sizeof(AT) == 4) {
                float2 f = *reinterpret_cast<const float2*>(
                    reinterpret_cast<const float*>(A) + (size_t)row * lda + k0 + cp * 2);
                hv = __floats2half2_rn(f.x, f.y);
            } else {
                hv = *reinterpret_cast<const __half2*>(
                    reinterpret_cast<const __half*>(A) + (size_t)row * lda + k0 + cp * 2);
            }
            reinterpret_cast<__half2*>(sA)[i] = hv;
        }
        __syncthreads();

        wmma::fragment<wmma::matrix_a, 16, 16, 16, __half, wmma::row_major> af[FM];
        #pragma unroll
        for (int i = 0; i < FM; i++)
            wmma::load_matrix_sync(af[i], sA + (wm * TM + i * 16) * 16, 16);
        wmma::fragment<wmma::matrix_b, 16, 16, 16, __half, wmma::row_major> bf[FN];
        #pragma unroll
        for (int j = 0; j < FN; j++)
            wmma::load_matrix_sync(bf[j], sB + k0 * BN + wn * TN + j * 16, BN);
        #pragma unroll
        for (int i = 0; i < FM; i++)
            #pragma unroll
            for (int j = 0; j < FN; j++)
                wmma::mma_sync(acc[i][j], af[i], bf[j], acc[i][j]);
    }

    float* scw = sC + wid * 256;
    const int r  = lane >> 1;
    const int c0 = (lane & 1) * 8;
    #pragma unroll
    for (int i = 0; i < FM; i++)
        #pragma unroll
        for (int j = 0; j < FN; j++) {
            wmma::store_matrix_sync(scw, acc[i][j], 16, wmma::mem_row_major);
            __syncwarp();
            float4 p0 = *reinterpret_cast<float4*>(scw + r * 16 + c0);
            float4 p1 = *reinterpret_cast<float4*>(scw + r * 16 + c0 + 4);
            const int row = bm + wm * TM + i * 16 + r;
            const int col = wn * TN + j * 16 + c0;
            if (ACC) {
                float4 a0 = *reinterpret_cast<const float4*>(
                    Cacc + (size_t)row * BN + col);
                float4 a1 = *reinterpret_cast<const float4*>(
                    Cacc + (size_t)row * BN + col + 4);
                p0.x += a0.x; p0.y += a0.y; p0.z += a0.z; p0.w += a0.w;
                p1.x += a1.x; p1.y += a1.y; p1.z += a1.z; p1.w += a1.w;
            }
            if (sizeof(OT) == 2) {
                __half2 h[4];
                h[0] = __floats2half2_rn(p0.x, p0.y);
                h[1] = __floats2half2_rn(p0.z, p0.w);
                h[2] = __floats2half2_rn(p1.x, p1.y);
                h[3] = __floats2half2_rn(p1.z, p1.w);
                *reinterpret_cast<uint4*>(
                    reinterpret_cast<__half*>(C) + (size_t)row * BN + col) =
                    *reinterpret_cast<uint4*>(h);
            } else {
                float* cp = reinterpret_cast<float*>(C) + (size_t)row * BN + col;
                *reinterpret_cast<float4*>(cp)     = p0;
                *reinterpret_cast<float4*>(cp + 4) = p1;
            }
            __syncwarp();
        }
}

// ---------------------------------------------------------------------------
// Fused: gemm1 (x@Wg1 -> h1) | Ux | Vx | hist    (D-GEMM moved to edgemlp)
// ---------------------------------------------------------------------------
__global__ void __launch_bounds__(256)
k_pre(const float* __restrict__ x, const int* __restrict__ ei,
      const float* __restrict__ Wg1, const float* __restrict__ Wm1,
      __half* __restrict__ h1, float* __restrict__ Uacc,
      float* __restrict__ Vacc) {
    const int bx = blockIdx.x;
    if (bx < GEMMB) {
        gemm_wmma<64, 128, float, false, __half>(
            x, 64, Wg1, h1, nullptr, NN, bx);
    } else if (bx < 2 * GEMMB) {
        gemm_wmma<64, 128, float, false, float>(
            x, 64, Wm1, Uacc, nullptr, NN, bx - GEMMB);
    } else if (bx < 3 * GEMMB) {
        gemm_wmma<64, 128, float, false, float>(
            x, 64, Wm1 + 128 * 128, Vacc, nullptr, NN, bx - 2 * GEMMB);
    } else {
        const int b = bx - 3 * GEMMB;
        for (int t = b * 256 + threadIdx.x; t < NE; t += HISTB * 256) {
            int2 rc = *reinterpret_cast<const int2*>(ei + 2 * t);
            atomicAdd(&g_deg[rc.x], 1);
            atomicAdd(&g_deg[rc.y], 1);
        }
    }
}

// ---------------------------------------------------------------------------
// Single-block scan over (deg + 1) + w~2 projection vectors.
// ---------------------------------------------------------------------------
__global__ void __launch_bounds__(1024)
k_scan(const float* __restrict__ Wg2, const float* __restrict__ a2s,
       const float* __restrict__ a2d) {
    constexpr int CH = (NN + 1023) / 1024;
    __shared__ int wsum[32];
    const int tid  = threadIdx.x;
    const int lane = tid & 31;
    const int wid  = tid >> 5;
    const int base = tid * CH;

    if (tid < 128) {
        float ws = 0.f, wd = 0.f;
        const float* r = Wg2 + tid * 64;
        #pragma unroll 8
        for (int j = 0; j < 64; j++) {
            float v = r[j];
            ws = fmaf(v, __ldg(a2s + j), ws);
            wd = fmaf(v, __ldg(a2d + j), wd);
        }
        g_w2s[tid] = ws;
        g_w2d[tid] = wd;
    }

    int vals[CH];
    int s = 0;
    #pragma unroll
    for (int k = 0; k < CH; k++) {
        int i = base + k;
        int v = (i < NN) ? g_deg[i] + 1 : 0;
        vals[k] = v;
        s += v;
    }
    int x = s;
    #pragma unroll
    for (int off = 1; off < 32; off <<= 1) {
        int y = __shfl_up_sync(0xffffffffu, x, off);
        if (lane >= off) x += y;
    }
    if (lane == 31) wsum[wid] = x;
    __syncthreads();
    if (wid == 0) {
        int w = wsum[lane];
        #pragma unroll
        for (int off = 1; off < 32; off <<= 1) {
            int y = __shfl_up_sync(0xffffffffu, w, off);
            if (lane >= off) w += y;
        }
        wsum[lane] = w;
    }
    __syncthreads();

    int run = x - s + (wid ? wsum[wid - 1] : 0);
    if (tid == 0) g_rowptr[0] = 0;
    #pragma unroll
    for (int k = 0; k < CH; k++) {
        int i = base + k;
        if (i < NN) {
            g_cursor[i] = run;
            run += vals[k];
            g_rowptr[i + 1] = run;
        }
    }
}

// ---------------------------------------------------------------------------
// Fused: CSR fill (single pass + self loops) | rowdots1 (h1 fp16)
// ---------------------------------------------------------------------------
__global__ void __launch_bounds__(256)
k_fill_rd(const int* __restrict__ ei,
          const float* __restrict__ a1s, const float* __restrict__ a1d) {
    const int bx = blockIdx.x;
    if (bx < FILLB) {
        const int total = NE + NN;
        for (int t = bx * 256 + threadIdx.x; t < total; t += FILLB * 256) {
            if (t < NE) {
                int2 rc = *reinterpret_cast<const int2*>(ei + 2 * t);
                int p1 = atomicAdd(&g_cursor[rc.y], 1);
                g_adj[p1] = rc.x;
                int p2 = atomicAdd(&g_cursor[rc.x], 1);
                g_adj[p2] = rc.y;
            } else {
                int n = t - NE;
                int p = atomicAdd(&g_cursor[n], 1);
                g_adj[p] = n;
            }
        }
    } else {
        const int w = ((bx - FILLB) * 256 + threadIdx.x) >> 5;
        const int lane = threadIdx.x & 31;
        if (w >= NN) return;
        const __half2* hr = reinterpret_cast<const __half2*>(g_h1 + (size_t)w * 128);
        float ds = 0.f, dt = 0.f;
        #pragma unroll
        for (int p = lane; p < 64; p += 32) {
            float2 v = __half22float2(hr[p]);
            ds = fmaf(v.x, __ldg(a1s + 2 * p), fmaf(v.y, __ldg(a1s + 2 * p + 1), ds));
            dt = fmaf(v.x, __ldg(a1d + 2 * p), fmaf(v.y, __ldg(a1d + 2 * p + 1), dt));
        }
        #pragma unroll
        for (int o = 16; o; o >>= 1) {
            ds += __shfl_xor_sync(0xffffffffu, ds, o);
            dt += __shfl_xor_sync(0xffffffffu, dt, o);
        }
        if (lane == 0) { g_s1[w] = ds; g_t1[w] = dt; }
    }
}

// ---------------------------------------------------------------------------
// GAT aggregation (R12-proven shape — DO NOT MODIFY).
// ---------------------------------------------------------------------------
template <int C>
__device__ __forceinline__ void gat_accum(const __half* __restrict__ h,
                                          int sk, float wk, int lane,
                                          float* acc) {
    if (C == 128) {
        uint2 raw = *reinterpret_cast<const uint2*>(h + (size_t)sk * C + lane * 4);
        float2 lo = __half22float2(*reinterpret_cast<__half2*>(&raw.x));
        float2 hi = __half22float2(*reinterpret_cast<__half2*>(&raw.y));
        acc[0] = fmaf(wk, lo.x, acc[0]);
        acc[1] = fmaf(wk, lo.y, acc[1]);
        acc[2] = fmaf(wk, hi.x, acc[2]);
        acc[3] = fmaf(wk, hi.y, acc[3]);
    } else {
        __half2 raw = *reinterpret_cast<const __half2*>(h + (size_t)sk * C + lane * 2);
        float2 v = __half22float2(raw);
        acc[0] = fmaf(wk, v.x, acc[0]);
        acc[1] = fmaf(wk, v.y, acc[1]);
    }
}

template <int C>
__global__ void k_gatagg(const __half* __restrict__ h,
                         const float* __restrict__ s,
                         const float* __restrict__ t,
                         const float* __restrict__ bias,
                         __half* __restrict__ outh) {
    constexpr int CPL = C / 32;
    int w = (blockIdx.x * blockDim.x + threadIdx.x) >> 5;
    int lane = threadIdx.x & 31;
    if (w >= NN) return;

    const int beg = g_rowptr[w];
    const int end = g_rowptr[w + 1];
    const float tn = t[w];

    float denom = 0.f;
    float acc[CPL];
    #pragma unroll
    for (int q = 0; q < CPL; q++) acc[q] = 0.f;

    int j0 = beg;
    for (; j0 + 32 <= end; j0 += 32) {
        int sj = g_adj[j0 + lane];
        float e = s[sj] + tn;
        e = (e >= 0.f) ? e : 0.2f * e;
        float wv = __expf(e);
        denom += wv;
        #pragma unroll
        for (int k = 0; k < 32; k++) {
            float wk = __shfl_sync(0xffffffffu, wv, k);
            int   sk = __shfl_sync(0xffffffffu, sj, k);
            gat_accum<C>(h, sk, wk, lane, acc);
        }
    }
    if (j0 < end) {
        int j = j0 + lane;
        float wv = 0.f;
        int sj = 0;
        if (j < end) {
            sj = g_adj[j];
            float e = s[sj] + tn;
            e = (e >= 0.f) ? e : 0.2f * e;
            wv = __expf(e);
        }
        denom += wv;
        int cnt = end - j0;
        for (int k = 0; k < cnt; k++) {
            float wk = __shfl_sync(0xffffffffu, wv, k);
            int   sk = __shfl_sync(0xffffffffu, sj, k);
            gat_accum<C>(h, sk, wk, lane, acc);
        }
    }
    #pragma unroll
    for (int o = 16; o; o >>= 1)
        denom += __shfl_xor_sync(0xffffffffu, denom, o);

    const float inv = 1.f / (denom + 1e-16f);
    if (CPL == 4) {
        __half2 hh[2];
        hh[0] = __floats2half2_rn(
            fmaxf(acc[0] * inv + __ldg(bias + lane * 4 + 0), 0.f),
            fmaxf(acc[1] * inv + __ldg(bias + lane * 4 + 1), 0.f));
        hh[1] = __floats2half2_rn(
            fmaxf(acc[2] * inv + __ldg(bias + lane * 4 + 2), 0.f),
            fmaxf(acc[3] * inv + __ldg(bias + lane * 4 + 3), 0.f));
        *reinterpret_cast<uint2*>(outh + (size_t)w * C + lane * 4) =
            *reinterpret_cast<uint2*>(hh);
    } else {
        __half2 hh = __floats2half2_rn(
            fmaxf(acc[0] * inv + __ldg(bias + lane * 2 + 0), 0.f),
            fmaxf(acc[1] * inv + __ldg(bias + lane * 2 + 1), 0.f));
        *reinterpret_cast<__half2*>(outh + (size_t)w * C + lane * 2) = hh;
    }
}

// ---------------------------------------------------------------------------
// Fused: gemm2 (f1 fp16 @ Wg2 -> h2 fp16) | rowdots2 (f1 fp16, w~2)
// ---------------------------------------------------------------------------
__global__ void __launch_bounds__(256)
k_sgemm2_rd(const __half* __restrict__ f1, const float* __restrict__ Wg2,
            __half* __restrict__ h2) {
    const int bx = blockIdx.x;
    if (bx < GEMMB) {
        gemm_wmma<128, 64, __half, false, __half>(
            f1, 128, Wg2, h2, nullptr, NN, bx);
    } else {
        const int w = ((bx - GEMMB) * 256 + threadIdx.x) >> 5;
        const int lane = threadIdx.x & 31;
        if (w >= NN) return;
        uint2 raw = *reinterpret_cast<const uint2*>(f1 + (size_t)w * 128 + lane * 4);
        float2 v01 = __half22float2(*reinterpret_cast<__half2*>(&raw.x));
        float2 v23 = __half22float2(*reinterpret_cast<__half2*>(&raw.y));
        float4 ws = *reinterpret_cast<const float4*>(g_w2s + lane * 4);
        float4 wd = *reinterpret_cast<const float4*>(g_w2d + lane * 4);
        float ds = v01.x * ws.x + v01.y * ws.y + v23.x * ws.z + v23.y * ws.w;
        float dt = v01.x * wd.x + v01.y * wd.y + v23.x * wd.z + v23.y * wd.w;
        #pragma unroll
        for (int o = 16; o; o >>= 1) {
            ds += __shfl_xor_sync(0xffffffffu, ds, o);
            dt += __shfl_xor_sync(0xffffffffu, dt, o);
        }
        if (lane == 0) { g_s2[w] = ds; g_t2[w] = dt; }
    }
}

// ---------------------------------------------------------------------------
// Fused U & V f-part GEMMs with accumulate from precomputed x-parts.
// ---------------------------------------------------------------------------
__global__ void __launch_bounds__(256)
k_uvf(const __half* __restrict__ f2, const float* __restrict__ Wm1,
      const float* __restrict__ Uacc, const float* __restrict__ Vacc,
      __half* __restrict__ U, __half* __restrict__ V) {
    if (blockIdx.y == 0)
        gemm_wmma<64, 128, __half, true, __half>(
            f2, 64, Wm1 + 64 * 128, U, Uacc, NN, blockIdx.x);
    else
        gemm_wmma<64, 128, __half, true, __half>(
            f2, 64, Wm1 + 192 * 128, V, Vacc, NN, blockIdx.x);
}

// ---------------------------------------------------------------------------
// Edge MLP with FUSED D-GEMM: block handles 128 edges.
//   Phase 1 (wmma): sD[128x128] = ed[e0:e0+128] @ W_d + b1   (fp16 smem)
//   Phase 2: per edge  a = relu_h2(U[row] + V[col] + sD[le]);
//            out = sigmoid(a . W_m2 + b2)
// No D tensor in DRAM at all.
// ---------------------------------------------------------------------------
__global__ void __launch_bounds__(256)
k_edgemlp(const int* __restrict__ ei, const float* __restrict__ ed,
          const float* __restrict__ Wd, const float* __restrict__ b1,
          const __half* __restrict__ U, const __half* __restrict__ V,
          const float* __restrict__ Wm2, const float* __restrict__ b2,
          float* __restrict__ out) {
    extern __shared__ unsigned char sm[];
    __half* sB = reinterpret_cast<__half*>(sm);                    // 16 x 128
    __half* sA = reinterpret_cast<__half*>(sm + 4096);             // 128 x 16
    __half* sD = reinterpret_cast<__half*>(sm + 8192);             // 128 x 128
    float*  sC = reinterpret_cast<float*>(sm + 8192 + 32768);      // 8 x 256

    const int tid  = threadIdx.x;
    const int lane = tid & 31;
    const int wid  = tid >> 5;
    const int wm   = wid >> 2, wn = wid & 3;    // 2 x 4 warp grid
    const int e0   = blockIdx.x * 128;

    // stage B (W_d, 16x128) and A (edge_dist rows e0..e0+127, 128x16) as fp16
    for (int i = tid; i < 16 * 128; i += 256)
        sB[i] = __float2half(Wd[i]);
    for (int i = tid; i < 128 * 8; i += 256) {
        int r = i >> 3, cp = i & 7;
        float2 f = *reinterpret_cast<const float2*>(
            ed + (size_t)(e0 + r) * 16 + cp * 2);
        reinterpret_cast<__half2*>(sA)[i] = __floats2half2_rn(f.x, f.y);
    }
    __syncthreads();

    // wmma: warp tile 64 x 32 (FM=4, FN=2), single K step (K=16)
    wmma::fragment<wmma::accumulator, 16, 16, 16, float> acc[4][2];
    wmma::fragment<wmma::matrix_b, 16, 16, 16, __half, wmma::row_major> bf[2];
    #pragma unroll
    for (int j = 0; j < 2; j++)
        wmma::load_matrix_sync(bf[j], sB + wn * 32 + j * 16, 128);
    #pragma unroll
    for (int i = 0; i < 4; i++) {
        wmma::fragment<wmma::matrix_a, 16, 16, 16, __half, wmma::row_major> af;
        wmma::load_matrix_sync(af, sA + (wm * 64 + i * 16) * 16, 16);
        #pragma unroll
        for (int j = 0; j < 2; j++) {
            wmma::fill_fragment(acc[i][j], 0.f);
            wmma::mma_sync(acc[i][j], af, bf[j], acc[i][j]);
        }
    }

    // epilogue: +b1, convert fp16, store into sD
    float* scw = sC + wid * 256;
    const int r  = lane >> 1;
    const int c0 = (lane & 1) * 8;
    #pragma unroll
    for (int i = 0; i < 4; i++)
        #pragma unroll
        for (int j = 0; j < 2; j++) {
            wmma::store_matrix_sync(scw, acc[i][j], 16, wmma::mem_row_major);
            __syncwarp();
            float4 p0 = *reinterpret_cast<float4*>(scw + r * 16 + c0);
            float4 p1 = *reinterpret_cast<float4*>(scw + r * 16 + c0 + 4);
            const int lrow = wm * 64 + i * 16 + r;
            const int col  = wn * 32 + j * 16 + c0;
            float4 b0  = *reinterpret_cast<const float4*>(b1 + col);
            float4 b1v = *reinterpret_cast<const float4*>(b1 + col + 4);
            p0.x += b0.x;  p0.y += b0.y;  p0.z += b0.z;  p0.w += b0.w;
            p1.x += b1v.x; p1.y += b1v.y; p1.z += b1v.z; p1.w += b1v.w;
            __half2 h[4];
            h[0] = __floats2half2_rn(p0.x, p0.y);
            h[1] = __floats2half2_rn(p0.z, p0.w);
            h[2] = __floats2half2_rn(p1.x, p1.y);
            h[3] = __floats2half2_rn(p1.z, p1.w);
            *reinterpret_cast<uint4*>(sD + lrow * 128 + col) =
                *reinterpret_cast<uint4*>(h);
            __syncwarp();
        }
    __syncthreads();

    // phase 2: warp wid handles edges le = wid*16 .. wid*16+15
    float4 w2r = *reinterpret_cast<const float4*>(Wm2 + lane * 4);
    const float b2v = __ldg(b2);
    const __half2 z2 = __floats2half2_rn(0.f, 0.f);

    #pragma unroll 2
    for (int q = 0; q < 16; q++) {
        const int le = wid * 16 + q;
        const int e  = e0 + le;
        int2 rc = *reinterpret_cast<const int2*>(ei + 2 * e);

        uint2 ur = *reinterpret_cast<const uint2*>(U + (size_t)rc.x * 128 + lane * 4);
        uint2 vr = *reinterpret_cast<const uint2*>(V + (size_t)rc.y * 128 + lane * 4);
        uint2 dr = *reinterpret_cast<const uint2*>(sD + le * 128 + lane * 4);

        __half2 u0 = *reinterpret_cast<__half2*>(&ur.x);
        __half2 u1 = *reinterpret_cast<__half2*>(&ur.y);
        __half2 v0 = *reinterpret_cast<__half2*>(&vr.x);
        __half2 v1 = *reinterpret_cast<__half2*>(&vr.y);
        __half2 d0 = *reinterpret_cast<__half2*>(&dr.x);
        __half2 d1 = *reinterpret_cast<__half2*>(&dr.y);

        __half2 s0 = __hmax2(__hadd2(__hadd2(u0, v0), d0), z2);
        __half2 s1 = __hmax2(__hadd2(__hadd2(u1, v1), d1), z2);

        float2 f0 = __half22float2(s0);
        float2 f1 = __half22float2(s1);
        float p = f0.x * w2r.x + f0.y * w2r.y + f1.x * w2r.z + f1.y * w2r.w;
        #pragma unroll
        for (int o = 16; o; o >>= 1)
            p += __shfl_xor_sync(0xffffffffu, p, o);

        if (lane == 0)
            out[e] = 1.f / (1.f + __expf(-(p + b2v)));
    }
}

// ---------------------------------------------------------------------------
extern "C" void kernel_launch(void* const* d_in, const int* in_sizes, int n_in,
                              void* d_out, int out_size) {
    const float* x    = (const float*)d_in[0];
    const int*   ei   = (const int*)  d_in[1];
    const float* ed   = (const float*)d_in[2];
    const float* Wg1  = (const float*)d_in[3];
    const float* a1s  = (const float*)d_in[4];
    const float* a1d  = (const float*)d_in[5];
    const float* bg1  = (const float*)d_in[6];
    const float* Wg2  = (const float*)d_in[7];
    const float* a2s  = (const float*)d_in[8];
    const float* a2d  = (const float*)d_in[9];
    const float* bg2  = (const float*)d_in[10];
    const float* Wm1  = (const float*)d_in[11];
    const float* bm1  = (const float*)d_in[12];
    const float* Wm2  = (const float*)d_in[13];
    const float* bm2  = (const float*)d_in[14];
    float* out = (float*)d_out;

    __half *h1, *f1, *h2, *f2, *U, *V;
    float *Uacc, *Vacc, *s1, *t1, *s2, *t2;
    int* degp;
    cudaGetSymbolAddress((void**)&h1, g_h1);
    cudaGetSymbolAddress((void**)&f1, g_f1);
    cudaGetSymbolAddress((void**)&h2, g_h2);
    cudaGetSymbolAddress((void**)&f2, g_f2);
    cudaGetSymbolAddress((void**)&U,  g_U);
    cudaGetSymbolAddress((void**)&V,  g_V);
    cudaGetSymbolAddress((void**)&Uacc, g_Uacc);
    cudaGetSymbolAddress((void**)&Vacc, g_Vacc);
    cudaGetSymbolAddress((void**)&s1, g_s1);
    cudaGetSymbolAddress((void**)&t1, g_t1);
    cudaGetSymbolAddress((void**)&s2, g_s2);
    cudaGetSymbolAddress((void**)&t2, g_t2);
    cudaGetSymbolAddress((void**)&degp, g_deg);

    cudaMemsetAsync(degp, 0, NN * sizeof(int));

    // gemm1 | Ux | Vx | hist
    k_pre<<<3 * GEMMB + HISTB, 256, GEMM_SMEM>>>(x, ei, Wg1, Wm1, h1, Uacc, Vacc);
    // scan (+self loops) + w~2
    k_scan<<<1, 1024>>>(Wg2, a2s, a2d);
    // fill | rowdots1
    k_fill_rd<<<FILLB + WB, 256>>>(ei, a1s, a1d);
    // GAT aggregate 1 -> f1 (fp16)
    k_gatagg<128><<<WB, 256>>>(h1, s1, t1, bg1, f1);
    // gemm2 | rowdots2
    k_sgemm2_rd<<<GEMMB + WB, 256, GEMM_SMEM>>>(f1, Wg2, h2);
    // GAT aggregate 2 -> f2 (fp16)
    k_gatagg<64><<<WB, 256>>>(h2, s2, t2, bg2, f2);
    // U/V f-part GEMMs + accumulate x-parts
    k_uvf<<<dim3(GEMMB, 2), 256, GEMM_SMEM>>>(f2, Wm1, Uacc, Vacc, U, V);
    // edge MLP with fused D-GEMM (no D in DRAM)
    k_edgemlp<<<EDGEB, 256, EMLP_SMEM>>>(ei, ed, Wm1 + 256 * 128, bm1,
                                         U, V, Wm2, bm2, out);
}

// round 16
// speedup vs baseline: 1.0835x; 1.0166x over previous
#include <cuda_runtime.h>
#include <cuda_fp16.h>
#include <mma.h>
#include <math.h>

using namespace nvcuda;

// ---------------------------------------------------------------------------
// GATEdgeNet: 2x GATConv (single head) + edge MLP.
// R15 winner + ONE change: unified fp16 xf16 = [x | f2] buffer.
// gatagg2 writes its output straight into xf16's right half, so U/V become
// single K=128 fp16 GEMMs — the fp32 Uacc/Vacc round-trip (102 MB) and two
// k_pre GEMM passes are deleted.
// ---------------------------------------------------------------------------

constexpr int NN  = 50000;
constexpr int NNP = 50048;
constexpr int NE  = 800000;
constexpr int ET  = 2 * NE + NN;

constexpr int GEMMB = NNP / 128;              // 391
constexpr int EDGEB = NE / 128;               // 6250 (exact)
constexpr int WB    = (NN * 32 + 255) / 256;  // 6250
constexpr int HISTB = 1024;
constexpr int COPYB = 512;
constexpr int FILLB = 1024;
constexpr int GEMM_SMEM = 64 * 128 * 2 + 128 * 16 * 2 + 8 * 256 * 4;   // 28672
constexpr int UVF_SMEM  = 128 * 128 * 2 + 128 * 16 * 2 + 8 * 256 * 4;  // 45056
// edgemlp: sB 4KB + sA 4KB + sD 32KB + sC 8KB = 48KB
constexpr int EMLP_SMEM = 16 * 128 * 2 + 128 * 16 * 2 + 128 * 128 * 2 + 8 * 256 * 4;

// ---- scratch ----------------------------------------------------------------
__device__ __half g_h1[NNP * 128];
__device__ __half g_f1[NN * 128];
__device__ __half g_h2[NNP * 64];
__device__ __half g_xf16[NNP * 128];   // [x (fp16) | f2] per node
__device__ __half g_U[NNP * 128];
__device__ __half g_V[NNP * 128];
__device__ float g_s1[NN];
__device__ float g_t1[NN];
__device__ float g_s2[NN];
__device__ float g_t2[NN];
__device__ float g_w2s[128];
__device__ float g_w2d[128];
__device__ int   g_deg[NN];
__device__ int   g_rowptr[NN + 1];
__device__ int   g_cursor[NN];
__device__ int   g_adj[ET];

// ---------------------------------------------------------------------------
// Tensor-core GEMM body (R12/R15-proven), dynamic smem, separate sC region.
// ---------------------------------------------------------------------------
template <int K, int BN, typename AT, typename OT>
__device__ __forceinline__ void gemm_wmma(const AT* __restrict__ A, int lda,
                                          const float* __restrict__ B,
                                          OT* __restrict__ C,
                                          int M, int bx) {
    constexpr int BM = 128;
    constexpr int WN = (BN == 128) ? 4 : 2;
    constexpr int WM = 8 / WN;
    constexpr int TM = BM / WM;
    constexpr int TN = BN / WN;
    constexpr int FM = TM / 16;
    constexpr int FN = TN / 16;

    extern __shared__ unsigned char dynsmem[];
    __half* sB = reinterpret_cast<__half*>(dynsmem);
    __half* sA = reinterpret_cast<__half*>(dynsmem + K * BN * 2);
    float*  sC = reinterpret_cast<float*>(dynsmem + K * BN * 2 + BM * 16 * 2);

    const int tid  = threadIdx.x;
    const int lane = tid & 31;
    const int wid  = tid >> 5;
    const int wm   = wid / WN, wn = wid % WN;
    const int bm   = bx * BM;

    for (int i = tid; i < K * BN; i += 256)
        sB[i] = __float2half(B[i]);

    wmma::fragment<wmma::accumulator, 16, 16, 16, float> acc[FM][FN];
    #pragma unroll
    for (int i = 0; i < FM; i++)
        #pragma unroll
        for (int j = 0; j < FN; j++)
            wmma::fill_fragment(acc[i][j], 0.f);

    #pragma unroll
    for (int k0 = 0; k0 < K; k0 += 16) {
        __syncthreads();
        #pragma unroll
        for (int i = tid; i < BM * 8; i += 256) {
            int r = i >> 3, cp = i & 7;
            int row = bm + r;
            if (row >= M) row = M - 1;
            __half2 hv;
            if (sizeof(AT) == 4) {
                float2 f = *reinterpret_cast<const float2*>(
                    reinterpret_cast<const float*>(A) + (size_t)row * lda + k0 + cp * 2);
                hv = __floats2half2_rn(f.x, f.y);
            } else {
                hv = *reinterpret_cast<const __half2*>(
                    reinterpret_cast<const __half*>(A) + (size_t)row * lda + k0 + cp * 2);
            }
            reinterpret_cast<__half2*>(sA)[i] = hv;
        }
        __syncthreads();

        wmma::fragment<wmma::matrix_a, 16, 16, 16, __half, wmma::row_major> af[FM];
        #pragma unroll
        for (int i = 0; i < FM; i++)
            wmma::load_matrix_sync(af[i], sA + (wm * TM + i * 16) * 16, 16);
        wmma::fragment<wmma::matrix_b, 16, 16, 16, __half, wmma::row_major> bf[FN];
        #pragma unroll
        for (int j = 0; j < FN; j++)
            wmma::load_matrix_sync(bf[j], sB + k0 * BN + wn * TN + j * 16, BN);
        #pragma unroll
        for (int i = 0; i < FM; i++)
            #pragma unroll
            for (int j = 0; j < FN; j++)
                wmma::mma_sync(acc[i][j], af[i], bf[j], acc[i][j]);
    }

    float* scw = sC + wid * 256;
    const int r  = lane >> 1;
    const int c0 = (lane & 1) * 8;
    #pragma unroll
    for (int i = 0; i < FM; i++)
        #pragma unroll
        for (int j = 0; j < FN; j++) {
            wmma::store_matrix_sync(scw, acc[i][j], 16, wmma::mem_row_major);
            __syncwarp();
            float4 p0 = *reinterpret_cast<float4*>(scw + r * 16 + c0);
            float4 p1 = *reinterpret_cast<float4*>(scw + r * 16 + c0 + 4);
            const int row = bm + wm * TM + i * 16 + r;
            const int col = wn * TN + j * 16 + c0;
            __half2 h[4];
            h[0] = __floats2half2_rn(p0.x, p0.y);
            h[1] = __floats2half2_rn(p0.z, p0.w);
            h[2] = __floats2half2_rn(p1.x, p1.y);
            h[3] = __floats2half2_rn(p1.z, p1.w);
            *reinterpret_cast<uint4*>(
                reinterpret_cast<__half*>(C) + (size_t)row * BN + col) =
                *reinterpret_cast<uint4*>(h);
            __syncwarp();
        }
}

// ---------------------------------------------------------------------------
// Fused: gemm1 (x@Wg1 -> h1) | x -> xf16 left half | hist
// ---------------------------------------------------------------------------
__global__ void __launch_bounds__(256)
k_pre(const float* __restrict__ x, const int* __restrict__ ei,
      const float* __restrict__ Wg1, __half* __restrict__ h1,
      __half* __restrict__ xf16) {
    const int bx = blockIdx.x;
    if (bx < GEMMB) {
        gemm_wmma<64, 128, float, __half>(x, 64, Wg1, h1, NN, bx);
    } else if (bx < GEMMB + COPYB) {
        const int b = bx - GEMMB;
        const int total = NN * 32;   // half2 count (64 fp16 per row)
        for (int i = b * 256 + threadIdx.x; i < total; i += COPYB * 256) {
            int r = i >> 5, c = i & 31;
            float2 f = reinterpret_cast<const float2*>(x)[i];
            *reinterpret_cast<__half2*>(xf16 + (size_t)r * 128 + c * 2) =
                __floats2half2_rn(f.x, f.y);
        }
    } else {
        const int b = bx - GEMMB - COPYB;
        for (int t = b * 256 + threadIdx.x; t < NE; t += HISTB * 256) {
            int2 rc = *reinterpret_cast<const int2*>(ei + 2 * t);
            atomicAdd(&g_deg[rc.x], 1);
            atomicAdd(&g_deg[rc.y], 1);
        }
    }
}

// ---------------------------------------------------------------------------
// Single-block scan over (deg + 1) + w~2 projection vectors.
// ---------------------------------------------------------------------------
__global__ void __launch_bounds__(1024)
k_scan(const float* __restrict__ Wg2, const float* __restrict__ a2s,
       const float* __restrict__ a2d) {
    constexpr int CH = (NN + 1023) / 1024;
    __shared__ int wsum[32];
    const int tid  = threadIdx.x;
    const int lane = tid & 31;
    const int wid  = tid >> 5;
    const int base = tid * CH;

    if (tid < 128) {
        float ws = 0.f, wd = 0.f;
        const float* r = Wg2 + tid * 64;
        #pragma unroll 8
        for (int j = 0; j < 64; j++) {
            float v = r[j];
            ws = fmaf(v, __ldg(a2s + j), ws);
            wd = fmaf(v, __ldg(a2d + j), wd);
        }
        g_w2s[tid] = ws;
        g_w2d[tid] = wd;
    }

    int vals[CH];
    int s = 0;
    #pragma unroll
    for (int k = 0; k < CH; k++) {
        int i = base + k;
        int v = (i < NN) ? g_deg[i] + 1 : 0;
        vals[k] = v;
        s += v;
    }
    int x = s;
    #pragma unroll
    for (int off = 1; off < 32; off <<= 1) {
        int y = __shfl_up_sync(0xffffffffu, x, off);
        if (lane >= off) x += y;
    }
    if (lane == 31) wsum[wid] = x;
    __syncthreads();
    if (wid == 0) {
        int w = wsum[lane];
        #pragma unroll
        for (int off = 1; off < 32; off <<= 1) {
            int y = __shfl_up_sync(0xffffffffu, w, off);
            if (lane >= off) w += y;
        }
        wsum[lane] = w;
    }
    __syncthreads();

    int run = x - s + (wid ? wsum[wid - 1] : 0);
    if (tid == 0) g_rowptr[0] = 0;
    #pragma unroll
    for (int k = 0; k < CH; k++) {
        int i = base + k;
        if (i < NN) {
            g_cursor[i] = run;
            run += vals[k];
            g_rowptr[i + 1] = run;
        }
    }
}

// ---------------------------------------------------------------------------
// Fused: CSR fill (single pass + self loops) | rowdots1 (h1 fp16)
// ---------------------------------------------------------------------------
__global__ void __launch_bounds__(256)
k_fill_rd(const int* __restrict__ ei,
          const float* __restrict__ a1s, const float* __restrict__ a1d) {
    const int bx = blockIdx.x;
    if (bx < FILLB) {
        const int total = NE + NN;
        for (int t = bx * 256 + threadIdx.x; t < total; t += FILLB * 256) {
            if (t < NE) {
                int2 rc = *reinterpret_cast<const int2*>(ei + 2 * t);
                int p1 = atomicAdd(&g_cursor[rc.y], 1);
                g_adj[p1] = rc.x;
                int p2 = atomicAdd(&g_cursor[rc.x], 1);
                g_adj[p2] = rc.y;
            } else {
                int n = t - NE;
                int p = atomicAdd(&g_cursor[n], 1);
                g_adj[p] = n;
            }
        }
    } else {
        const int w = ((bx - FILLB) * 256 + threadIdx.x) >> 5;
        const int lane = threadIdx.x & 31;
        if (w >= NN) return;
        const __half2* hr = reinterpret_cast<const __half2*>(g_h1 + (size_t)w * 128);
        float ds = 0.f, dt = 0.f;
        #pragma unroll
        for (int p = lane; p < 64; p += 32) {
            float2 v = __half22float2(hr[p]);
            ds = fmaf(v.x, __ldg(a1s + 2 * p), fmaf(v.y, __ldg(a1s + 2 * p + 1), ds));
            dt = fmaf(v.x, __ldg(a1d + 2 * p), fmaf(v.y, __ldg(a1d + 2 * p + 1), dt));
        }
        #pragma unroll
        for (int o = 16; o; o >>= 1) {
            ds += __shfl_xor_sync(0xffffffffu, ds, o);
            dt += __shfl_xor_sync(0xffffffffu, dt, o);
        }
        if (lane == 0) { g_s1[w] = ds; g_t1[w] = dt; }
    }
}

// ---------------------------------------------------------------------------
// GAT aggregation (R12-proven shape — DO NOT MODIFY the loop body).
// Output stride/offset are compile-time template params (zero register cost):
// gatagg1 writes compact f1; gatagg2 writes xf16's right half.
// ---------------------------------------------------------------------------
template <int C>
__device__ __forceinline__ void gat_accum(const __half* __restrict__ h,
                                          int sk, float wk, int lane,
                                          float* acc) {
    if (C == 128) {
        uint2 raw = *reinterpret_cast<const uint2*>(h + (size_t)sk * C + lane * 4);
        float2 lo = __half22float2(*reinterpret_cast<__half2*>(&raw.x));
        float2 hi = __half22float2(*reinterpret_cast<__half2*>(&raw.y));
        acc[0] = fmaf(wk, lo.x, acc[0]);
        acc[1] = fmaf(wk, lo.y, acc[1]);
        acc[2] = fmaf(wk, hi.x, acc[2]);
        acc[3] = fmaf(wk, hi.y, acc[3]);
    } else {
        __half2 raw = *reinterpret_cast<const __half2*>(h + (size_t)sk * C + lane * 2);
        float2 v = __half22float2(raw);
        acc[0] = fmaf(wk, v.x, acc[0]);
        acc[1] = fmaf(wk, v.y, acc[1]);
    }
}

template <int C, int OSTR, int OCOL>
__global__ void k_gatagg(const __half* __restrict__ h,
                         const float* __restrict__ s,
                         const float* __restrict__ t,
                         const float* __restrict__ bias,
                         __half* __restrict__ outh) {
    constexpr int CPL = C / 32;
    int w = (blockIdx.x * blockDim.x + threadIdx.x) >> 5;
    int lane = threadIdx.x & 31;
    if (w >= NN) return;

    const int beg = g_rowptr[w];
    const int end = g_rowptr[w + 1];
    const float tn = t[w];

    float denom = 0.f;
    float acc[CPL];
    #pragma unroll
    for (int q = 0; q < CPL; q++) acc[q] = 0.f;

    int j0 = beg;
    for (; j0 + 32 <= end; j0 += 32) {
        int sj = g_adj[j0 + lane];
        float e = s[sj] + tn;
        e = (e >= 0.f) ? e : 0.2f * e;
        float wv = __expf(e);
        denom += wv;
        #pragma unroll
        for (int k = 0; k < 32; k++) {
            float wk = __shfl_sync(0xffffffffu, wv, k);
            int   sk = __shfl_sync(0xffffffffu, sj, k);
            gat_accum<C>(h, sk, wk, lane, acc);
        }
    }
    if (j0 < end) {
        int j = j0 + lane;
        float wv = 0.f;
        int sj = 0;
        if (j < end) {
            sj = g_adj[j];
            float e = s[sj] + tn;
            e = (e >= 0.f) ? e : 0.2f * e;
            wv = __expf(e);
        }
        denom += wv;
        int cnt = end - j0;
        for (int k = 0; k < cnt; k++) {
            float wk = __shfl_sync(0xffffffffu, wv, k);
            int   sk = __shfl_sync(0xffffffffu, sj, k);
            gat_accum<C>(h, sk, wk, lane, acc);
        }
    }
    #pragma unroll
    for (int o = 16; o; o >>= 1)
        denom += __shfl_xor_sync(0xffffffffu, denom, o);

    const float inv = 1.f / (denom + 1e-16f);
    if (CPL == 4) {
        __half2 hh[2];
        hh[0] = __floats2half2_rn(
            fmaxf(acc[0] * inv + __ldg(bias + lane * 4 + 0), 0.f),
            fmaxf(acc[1] * inv + __ldg(bias + lane * 4 + 1), 0.f));
        hh[1] = __floats2half2_rn(
            fmaxf(acc[2] * inv + __ldg(bias + lane * 4 + 2), 0.f),
            fmaxf(acc[3] * inv + __ldg(bias + lane * 4 + 3), 0.f));
        *reinterpret_cast<uint2*>(outh + (size_t)w * OSTR + OCOL + lane * 4) =
            *reinterpret_cast<uint2*>(hh);
    } else {
        __half2 hh = __floats2half2_rn(
            fmaxf(acc[0] * inv + __ldg(bias + lane * 2 + 0), 0.f),
            fmaxf(acc[1] * inv + __ldg(bias + lane * 2 + 1), 0.f));
        *reinterpret_cast<__half2*>(outh + (size_t)w * OSTR + OCOL + lane * 2) = hh;
    }
}

// ---------------------------------------------------------------------------
// Fused: gemm2 (f1 fp16 @ Wg2 -> h2 fp16) | rowdots2 (f1 fp16, w~2)
// ---------------------------------------------------------------------------
__global__ void __launch_bounds__(256)
k_sgemm2_rd(const __half* __restrict__ f1, const float* __restrict__ Wg2,
            __half* __restrict__ h2) {
    const int bx = blockIdx.x;
    if (bx < GEMMB) {
        gemm_wmma<128, 64, __half, __half>(f1, 128, Wg2, h2, NN, bx);
    } else {
        const int w = ((bx - GEMMB) * 256 + threadIdx.x) >> 5;
        const int lane = threadIdx.x & 31;
        if (w >= NN) return;
        uint2 raw = *reinterpret_cast<const uint2*>(f1 + (size_t)w * 128 + lane * 4);
        float2 v01 = __half22float2(*reinterpret_cast<__half2*>(&raw.x));
        float2 v23 = __half22float2(*reinterpret_cast<__half2*>(&raw.y));
        float4 ws = *reinterpret_cast<const float4*>(g_w2s + lane * 4);
        float4 wd = *reinterpret_cast<const float4*>(g_w2d + lane * 4);
        float ds = v01.x * ws.x + v01.y * ws.y + v23.x * ws.z + v23.y * ws.w;
        float dt = v01.x * wd.x + v01.y * wd.y + v23.x * wd.z + v23.y * wd.w;
        #pragma unroll
        for (int o = 16; o; o >>= 1) {
            ds += __shfl_xor_sync(0xffffffffu, ds, o);
            dt += __shfl_xor_sync(0xffffffffu, dt, o);
        }
        if (lane == 0) { g_s2[w] = ds; g_t2[w] = dt; }
    }
}

// ---------------------------------------------------------------------------
// U & V as single K=128 fp16 GEMMs over xf16 = [x | f2].
// ---------------------------------------------------------------------------
__global__ void __launch_bounds__(256)
k_uvf(const __half* __restrict__ xf16, const float* __restrict__ Wm1,
      __half* __restrict__ U, __half* __restrict__ V) {
    if (blockIdx.y == 0)
        gemm_wmma<128, 128, __half, __half>(xf16, 128, Wm1, U, NN, blockIdx.x);
    else
        gemm_wmma<128, 128, __half, __half>(xf16, 128, Wm1 + 128 * 128, V,
                                            NN, blockIdx.x);
}

// ---------------------------------------------------------------------------
// Edge MLP with FUSED D-GEMM (R15-proven): block handles 128 edges.
// ---------------------------------------------------------------------------
__global__ void __launch_bounds__(256)
k_edgemlp(const int* __restrict__ ei, const float* __restrict__ ed,
          const float* __restrict__ Wd, const float* __restrict__ b1,
          const __half* __restrict__ U, const __half* __restrict__ V,
          const float* __restrict__ Wm2, const float* __restrict__ b2,
          float* __restrict__ out) {
    extern __shared__ unsigned char sm[];
    __half* sB = reinterpret_cast<__half*>(sm);                    // 16 x 128
    __half* sA = reinterpret_cast<__half*>(sm + 4096);             // 128 x 16
    __half* sD = reinterpret_cast<__half*>(sm + 8192);             // 128 x 128
    float*  sC = reinterpret_cast<float*>(sm + 8192 + 32768);      // 8 x 256

    const int tid  = threadIdx.x;
    const int lane = tid & 31;
    const int wid  = tid >> 5;
    const int wm   = wid >> 2, wn = wid & 3;
    const int e0   = blockIdx.x * 128;

    for (int i = tid; i < 16 * 128; i += 256)
        sB[i] = __float2half(Wd[i]);
    for (int i = tid; i < 128 * 8; i += 256) {
        int r = i >> 3, cp = i & 7;
        float2 f = *reinterpret_cast<const float2*>(
            ed + (size_t)(e0 + r) * 16 + cp * 2);
        reinterpret_cast<__half2*>(sA)[i] = __floats2half2_rn(f.x, f.y);
    }
    __syncthreads();

    wmma::fragment<wmma::accumulator, 16, 16, 16, float> acc[4][2];
    wmma::fragment<wmma::matrix_b, 16, 16, 16, __half, wmma::row_major> bf[2];
    #pragma unroll
    for (int j = 0; j < 2; j++)
        wmma::load_matrix_sync(bf[j], sB + wn * 32 + j * 16, 128);
    #pragma unroll
    for (int i = 0; i < 4; i++) {
        wmma::fragment<wmma::matrix_a, 16, 16, 16, __half, wmma::row_major> af;
        wmma::load_matrix_sync(af, sA + (wm * 64 + i * 16) * 16, 16);
        #pragma unroll
        for (int j = 0; j < 2; j++) {
            wmma::fill_fragment(acc[i][j], 0.f);
            wmma::mma_sync(acc[i][j], af, bf[j], acc[i][j]);
        }
    }

    float* scw = sC + wid * 256;
    const int r  = lane >> 1;
    const int c0 = (lane & 1) * 8;
    #pragma unroll
    for (int i = 0; i < 4; i++)
        #pragma unroll
        for (int j = 0; j < 2; j++) {
            wmma::store_matrix_sync(scw, acc[i][j], 16, wmma::mem_row_major);
            __syncwarp();
            float4 p0 = *reinterpret_cast<float4*>(scw + r * 16 + c0);
            float4 p1 = *reinterpret_cast<float4*>(scw + r * 16 + c0 + 4);
            const int lrow = wm * 64 + i * 16 + r;
            const int col  = wn * 32 + j * 16 + c0;
            float4 b0  = *reinterpret_cast<const float4*>(b1 + col);
            float4 b1v = *reinterpret_cast<const float4*>(b1 + col + 4);
            p0.x += b0.x;  p0.y += b0.y;  p0.z += b0.z;  p0.w += b0.w;
            p1.x += b1v.x; p1.y += b1v.y; p1.z += b1v.z; p1.w += b1v.w;
            __half2 h[4];
            h[0] = __floats2half2_rn(p0.x, p0.y);
            h[1] = __floats2half2_rn(p0.z, p0.w);
            h[2] = __floats2half2_rn(p1.x, p1.y);
            h[3] = __floats2half2_rn(p1.z, p1.w);
            *reinterpret_cast<uint4*>(sD + lrow * 128 + col) =
                *reinterpret_cast<uint4*>(h);
            __syncwarp();
        }
    __syncthreads();

    float4 w2r = *reinterpret_cast<const float4*>(Wm2 + lane * 4);
    const float b2v = __ldg(b2);
    const __half2 z2 = __floats2half2_rn(0.f, 0.f);

    #pragma unroll 2
    for (int q = 0; q < 16; q++) {
        const int le = wid * 16 + q;
        const int e  = e0 + le;
        int2 rc = *reinterpret_cast<const int2*>(ei + 2 * e);

        uint2 ur = *reinterpret_cast<const uint2*>(U + (size_t)rc.x * 128 + lane * 4);
        uint2 vr = *reinterpret_cast<const uint2*>(V + (size_t)rc.y * 128 + lane * 4);
        uint2 dr = *reinterpret_cast<const uint2*>(sD + le * 128 + lane * 4);

        __half2 u0 = *reinterpret_cast<__half2*>(&ur.x);
        __half2 u1 = *reinterpret_cast<__half2*>(&ur.y);
        __half2 v0 = *reinterpret_cast<__half2*>(&vr.x);
        __half2 v1 = *reinterpret_cast<__half2*>(&vr.y);
        __half2 d0 = *reinterpret_cast<__half2*>(&dr.x);
        __half2 d1 = *reinterpret_cast<__half2*>(&dr.y);

        __half2 s0 = __hmax2(__hadd2(__hadd2(u0, v0), d0), z2);
        __half2 s1 = __hmax2(__hadd2(__hadd2(u1, v1), d1), z2);

        float2 f0 = __half22float2(s0);
        float2 f1 = __half22float2(s1);
        float p = f0.x * w2r.x + f0.y * w2r.y + f1.x * w2r.z + f1.y * w2r.w;
        #pragma unroll
        for (int o = 16; o; o >>= 1)
            p += __shfl_xor_sync(0xffffffffu, p, o);

        if (lane == 0)
            out[e] = 1.f / (1.f + __expf(-(p + b2v)));
    }
}

// ---------------------------------------------------------------------------
extern "C" void kernel_launch(void* const* d_in, const int* in_sizes, int n_in,
                              void* d_out, int out_size) {
    const float* x    = (const float*)d_in[0];
    const int*   ei   = (const int*)  d_in[1];
    const float* ed   = (const float*)d_in[2];
    const float* Wg1  = (const float*)d_in[3];
    const float* a1s  = (const float*)d_in[4];
    const float* a1d  = (const float*)d_in[5];
    const float* bg1  = (const float*)d_in[6];
    const float* Wg2  = (const float*)d_in[7];
    const float* a2s  = (const float*)d_in[8];
    const float* a2d  = (const float*)d_in[9];
    const float* bg2  = (const float*)d_in[10];
    const float* Wm1  = (const float*)d_in[11];
    const float* bm1  = (const float*)d_in[12];
    const float* Wm2  = (const float*)d_in[13];
    const float* bm2  = (const float*)d_in[14];
    float* out = (float*)d_out;

    __half *h1, *f1, *h2, *xf16, *U, *V;
    float *s1, *t1, *s2, *t2;
    int* degp;
    cudaGetSymbolAddress((void**)&h1, g_h1);
    cudaGetSymbolAddress((void**)&f1, g_f1);
    cudaGetSymbolAddress((void**)&h2, g_h2);
    cudaGetSymbolAddress((void**)&xf16, g_xf16);
    cudaGetSymbolAddress((void**)&U,  g_U);
    cudaGetSymbolAddress((void**)&V,  g_V);
    cudaGetSymbolAddress((void**)&s1, g_s1);
    cudaGetSymbolAddress((void**)&t1, g_t1);
    cudaGetSymbolAddress((void**)&s2, g_s2);
    cudaGetSymbolAddress((void**)&t2, g_t2);
    cudaGetSymbolAddress((void**)&degp, g_deg);

    cudaMemsetAsync(degp, 0, NN * sizeof(int));

    // gemm1 | x->xf16 | hist
    k_pre<<<GEMMB + COPYB + HISTB, 256, GEMM_SMEM>>>(x, ei, Wg1, h1, xf16);
    // scan (+self loops) + w~2
    k_scan<<<1, 1024>>>(Wg2, a2s, a2d);
    // fill | rowdots1
    k_fill_rd<<<FILLB + WB, 256>>>(ei, a1s, a1d);
    // GAT aggregate 1 -> f1 (fp16, compact)
    k_gatagg<128, 128, 0><<<WB, 256>>>(h1, s1, t1, bg1, f1);
    // gemm2 | rowdots2
    k_sgemm2_rd<<<GEMMB + WB, 256, GEMM_SMEM>>>(f1, Wg2, h2);
    // GAT aggregate 2 -> xf16 right half
    k_gatagg<64, 128, 64><<<WB, 256>>>(h2, s2, t2, bg2, xf16);
    // U and V: single K=128 fp16 GEMMs over xf16
    k_uvf<<<dim3(GEMMB, 2), 256, UVF_SMEM>>>(xf16, Wm1, U, V);
    // edge MLP with fused D-GEMM
    k_edgemlp<<<EDGEB, 256, EMLP_SMEM>>>(ei, ed, Wm1 + 256 * 128, bm1,
                                         U, V, Wm2, bm2, out);
}

// round 17
// speedup vs baseline: 1.0919x; 1.0077x over previous
#include <cuda_runtime.h>
#include <cuda_fp16.h>
#include <mma.h>
#include <math.h>

using namespace nvcuda;

// ---------------------------------------------------------------------------
// GATEdgeNet: 2x GATConv (single head) + edge MLP.
// R16 winner + ONE change: double-buffered A staging in gemm_wmma
// (one barrier per k-step instead of two; staging overlaps MMA).
// ---------------------------------------------------------------------------

constexpr int NN  = 50000;
constexpr int NNP = 50048;
constexpr int NE  = 800000;
constexpr int ET  = 2 * NE + NN;

constexpr int GEMMB = NNP / 128;              // 391
constexpr int EDGEB = NE / 128;               // 6250 (exact)
constexpr int WB    = (NN * 32 + 255) / 256;  // 6250
constexpr int HISTB = 1024;
constexpr int COPYB = 512;
constexpr int FILLB = 1024;
// gemm smem: sB (K*BN fp16) + 2 x sA (128x16 fp16) + sC (8x256 fp32)
constexpr int GEMM_SMEM = 64 * 128 * 2 + 2 * 128 * 16 * 2 + 8 * 256 * 4;   // 32768
constexpr int UVF_SMEM  = 128 * 128 * 2 + 2 * 128 * 16 * 2 + 8 * 256 * 4;  // 49152
// edgemlp: sB 4KB + sA 4KB + sD 32KB + sC 8KB = 48KB
constexpr int EMLP_SMEM = 16 * 128 * 2 + 128 * 16 * 2 + 128 * 128 * 2 + 8 * 256 * 4;

// ---- scratch ----------------------------------------------------------------
__device__ __half g_h1[NNP * 128];
__device__ __half g_f1[NN * 128];
__device__ __half g_h2[NNP * 64];
__device__ __half g_xf16[NNP * 128];   // [x (fp16) | f2] per node
__device__ __half g_U[NNP * 128];
__device__ __half g_V[NNP * 128];
__device__ float g_s1[NN];
__device__ float g_t1[NN];
__device__ float g_s2[NN];
__device__ float g_t2[NN];
__device__ float g_w2s[128];
__device__ float g_w2d[128];
__device__ int   g_deg[NN];
__device__ int   g_rowptr[NN + 1];
__device__ int   g_cursor[NN];
__device__ int   g_adj[ET];

// ---------------------------------------------------------------------------
// Tensor-core GEMM body, double-buffered A staging.
// ---------------------------------------------------------------------------
template <int K, int BN, typename AT, typename OT>
__device__ __forceinline__ void gemm_wmma(const AT* __restrict__ A, int lda,
                                          const float* __restrict__ B,
                                          OT* __restrict__ C,
                                          int M, int bx) {
    constexpr int BM = 128;
    constexpr int WN = (BN == 128) ? 4 : 2;
    constexpr int WM = 8 / WN;
    constexpr int TM = BM / WM;
    constexpr int TN = BN / WN;
    constexpr int FM = TM / 16;
    constexpr int FN = TN / 16;
    constexpr int NSTEP = K / 16;

    extern __shared__ unsigned char dynsmem[];
    __half* sB = reinterpret_cast<__half*>(dynsmem);
    __half* sA = reinterpret_cast<__half*>(dynsmem + K * BN * 2);   // 2 buffers
    float*  sC = reinterpret_cast<float*>(dynsmem + K * BN * 2 + 2 * BM * 16 * 2);

    const int tid  = threadIdx.x;
    const int lane = tid & 31;
    const int wid  = tid >> 5;
    const int wm   = wid / WN, wn = wid % WN;
    const int bm   = bx * BM;

    for (int i = tid; i < K * BN; i += 256)
        sB[i] = __float2half(B[i]);

    // stage A tile for k-step `st` into buffer `bf`
    auto stageA = [&](int st, int bf) {
        const int k0 = st * 16;
        __half2* dst = reinterpret_cast<__half2*>(sA + bf * BM * 16);
        #pragma unroll
        for (int i = tid; i < BM * 8; i += 256) {
            int r = i >> 3, cp = i & 7;
            int row = bm + r;
            if (row >= M) row = M - 1;
            __half2 hv;
            if (sizeof(AT) == 4) {
                float2 f = *reinterpret_cast<const float2*>(
                    reinterpret_cast<const float*>(A) + (size_t)row * lda + k0 + cp * 2);
                hv = __floats2half2_rn(f.x, f.y);
            } else {
                hv = *reinterpret_cast<const __half2*>(
                    reinterpret_cast<const __half*>(A) + (size_t)row * lda + k0 + cp * 2);
            }
            dst[i] = hv;
        }
    };

    wmma::fragment<wmma::accumulator, 16, 16, 16, float> acc[FM][FN];
    #pragma unroll
    for (int i = 0; i < FM; i++)
        #pragma unroll
        for (int j = 0; j < FN; j++)
            wmma::fill_fragment(acc[i][j], 0.f);

    stageA(0, 0);
    __syncthreads();

    int buf = 0;
    #pragma unroll
    for (int step = 0; step < NSTEP; step++) {
        if (step + 1 < NSTEP) stageA(step + 1, buf ^ 1);  // overlaps MMA below

        const __half* sAc = sA + buf * BM * 16;
        const int k0 = step * 16;
        wmma::fragment<wmma::matrix_a, 16, 16, 16, __half, wmma::row_major> af[FM];
        #pragma unroll
        for (int i = 0; i < FM; i++)
            wmma::load_matrix_sync(af[i], sAc + (wm * TM + i * 16) * 16, 16);
        wmma::fragment<wmma::matrix_b, 16, 16, 16, __half, wmma::row_major> bf[FN];
        #pragma unroll
        for (int j = 0; j < FN; j++)
            wmma::load_matrix_sync(bf[j], sB + k0 * BN + wn * TN + j * 16, BN);
        #pragma unroll
        for (int i = 0; i < FM; i++)
            #pragma unroll
            for (int j = 0; j < FN; j++)
                wmma::mma_sync(acc[i][j], af[i], bf[j], acc[i][j]);

        __syncthreads();
        buf ^= 1;
    }

    float* scw = sC + wid * 256;
    const int r  = lane >> 1;
    const int c0 = (lane & 1) * 8;
    #pragma unroll
    for (int i = 0; i < FM; i++)
        #pragma unroll
        for (int j = 0; j < FN; j++) {
            wmma::store_matrix_sync(scw, acc[i][j], 16, wmma::mem_row_major);
            __syncwarp();
            float4 p0 = *reinterpret_cast<float4*>(scw + r * 16 + c0);
            float4 p1 = *reinterpret_cast<float4*>(scw + r * 16 + c0 + 4);
            const int row = bm + wm * TM + i * 16 + r;
            const int col = wn * TN + j * 16 + c0;
            __half2 h[4];
            h[0] = __floats2half2_rn(p0.x, p0.y);
            h[1] = __floats2half2_rn(p0.z, p0.w);
            h[2] = __floats2half2_rn(p1.x, p1.y);
            h[3] = __floats2half2_rn(p1.z, p1.w);
            *reinterpret_cast<uint4*>(
                reinterpret_cast<__half*>(C) + (size_t)row * BN + col) =
                *reinterpret_cast<uint4*>(h);
            __syncwarp();
        }
}

// ---------------------------------------------------------------------------
// Fused: gemm1 (x@Wg1 -> h1) | x -> xf16 left half | hist
// ---------------------------------------------------------------------------
__global__ void __launch_bounds__(256)
k_pre(const float* __restrict__ x, const int* __restrict__ ei,
      const float* __restrict__ Wg1, __half* __restrict__ h1,
      __half* __restrict__ xf16) {
    const int bx = blockIdx.x;
    if (bx < GEMMB) {
        gemm_wmma<64, 128, float, __half>(x, 64, Wg1, h1, NN, bx);
    } else if (bx < GEMMB + COPYB) {
        const int b = bx - GEMMB;
        const int total = NN * 32;   // half2 count (64 fp16 per row)
        for (int i = b * 256 + threadIdx.x; i < total; i += COPYB * 256) {
            int r = i >> 5, c = i & 31;
            float2 f = reinterpret_cast<const float2*>(x)[i];
            *reinterpret_cast<__half2*>(xf16 + (size_t)r * 128 + c * 2) =
                __floats2half2_rn(f.x, f.y);
        }
    } else {
        const int b = bx - GEMMB - COPYB;
        for (int t = b * 256 + threadIdx.x; t < NE; t += HISTB * 256) {
            int2 rc = *reinterpret_cast<const int2*>(ei + 2 * t);
            atomicAdd(&g_deg[rc.x], 1);
            atomicAdd(&g_deg[rc.y], 1);
        }
    }
}

// ---------------------------------------------------------------------------
// Single-block scan over (deg + 1) + w~2 projection vectors.
// ---------------------------------------------------------------------------
__global__ void __launch_bounds__(1024)
k_scan(const float* __restrict__ Wg2, const float* __restrict__ a2s,
       const float* __restrict__ a2d) {
    constexpr int CH = (NN + 1023) / 1024;
    __shared__ int wsum[32];
    const int tid  = threadIdx.x;
    const int lane = tid & 31;
    const int wid  = tid >> 5;
    const int base = tid * CH;

    if (tid < 128) {
        float ws = 0.f, wd = 0.f;
        const float* r = Wg2 + tid * 64;
        #pragma unroll 8
        for (int j = 0; j < 64; j++) {
            float v = r[j];
            ws = fmaf(v, __ldg(a2s + j), ws);
            wd = fmaf(v, __ldg(a2d + j), wd);
        }
        g_w2s[tid] = ws;
        g_w2d[tid] = wd;
    }

    int vals[CH];
    int s = 0;
    #pragma unroll
    for (int k = 0; k < CH; k++) {
        int i = base + k;
        int v = (i < NN) ? g_deg[i] + 1 : 0;
        vals[k] = v;
        s += v;
    }
    int x = s;
    #pragma unroll
    for (int off = 1; off < 32; off <<= 1) {
        int y = __shfl_up_sync(0xffffffffu, x, off);
        if (lane >= off) x += y;
    }
    if (lane == 31) wsum[wid] = x;
    __syncthreads();
    if (wid == 0) {
        int w = wsum[lane];
        #pragma unroll
        for (int off = 1; off < 32; off <<= 1) {
            int y = __shfl_up_sync(0xffffffffu, w, off);
            if (lane >= off) w += y;
        }
        wsum[lane] = w;
    }
    __syncthreads();

    int run = x - s + (wid ? wsum[wid - 1] : 0);
    if (tid == 0) g_rowptr[0] = 0;
    #pragma unroll
    for (int k = 0; k < CH; k++) {
        int i = base + k;
        if (i < NN) {
            g_cursor[i] = run;
            run += vals[k];
            g_rowptr[i + 1] = run;
        }
    }
}

// ---------------------------------------------------------------------------
// Fused: CSR fill (single pass + self loops) | rowdots1 (h1 fp16)
// ---------------------------------------------------------------------------
__global__ void __launch_bounds__(256)
k_fill_rd(const int* __restrict__ ei,
          const float* __restrict__ a1s, const float* __restrict__ a1d) {
    const int bx = blockIdx.x;
    if (bx < FILLB) {
        const int total = NE + NN;
        for (int t = bx * 256 + threadIdx.x; t < total; t += FILLB * 256) {
            if (t < NE) {
                int2 rc = *reinterpret_cast<const int2*>(ei + 2 * t);
                int p1 = atomicAdd(&g_cursor[rc.y], 1);
                g_adj[p1] = rc.x;
                int p2 = atomicAdd(&g_cursor[rc.x], 1);
                g_adj[p2] = rc.y;
            } else {
                int n = t - NE;
                int p = atomicAdd(&g_cursor[n], 1);
                g_adj[p] = n;
            }
        }
    } else {
        const int w = ((bx - FILLB) * 256 + threadIdx.x) >> 5;
        const int lane = threadIdx.x & 31;
        if (w >= NN) return;
        const __half2* hr = reinterpret_cast<const __half2*>(g_h1 + (size_t)w * 128);
        float ds = 0.f, dt = 0.f;
        #pragma unroll
        for (int p = lane; p < 64; p += 32) {
            float2 v = __half22float2(hr[p]);
            ds = fmaf(v.x, __ldg(a1s + 2 * p), fmaf(v.y, __ldg(a1s + 2 * p + 1), ds));
            dt = fmaf(v.x, __ldg(a1d + 2 * p), fmaf(v.y, __ldg(a1d + 2 * p + 1), dt));
        }
        #pragma unroll
        for (int o = 16; o; o >>= 1) {
            ds += __shfl_xor_sync(0xffffffffu, ds, o);
            dt += __shfl_xor_sync(0xffffffffu, dt, o);
        }
        if (lane == 0) { g_s1[w] = ds; g_t1[w] = dt; }
    }
}

// ---------------------------------------------------------------------------
// GAT aggregation (R12-proven shape — DO NOT MODIFY the loop body).
// ---------------------------------------------------------------------------
template <int C>
__device__ __forceinline__ void gat_accum(const __half* __restrict__ h,
                                          int sk, float wk, int lane,
                                          float* acc) {
    if (C == 128) {
        uint2 raw = *reinterpret_cast<const uint2*>(h + (size_t)sk * C + lane * 4);
        float2 lo = __half22float2(*reinterpret_cast<__half2*>(&raw.x));
        float2 hi = __half22float2(*reinterpret_cast<__half2*>(&raw.y));
        acc[0] = fmaf(wk, lo.x, acc[0]);
        acc[1] = fmaf(wk, lo.y, acc[1]);
        acc[2] = fmaf(wk, hi.x, acc[2]);
        acc[3] = fmaf(wk, hi.y, acc[3]);
    } else {
        __half2 raw = *reinterpret_cast<const __half2*>(h + (size_t)sk * C + lane * 2);
        float2 v = __half22float2(raw);
        acc[0] = fmaf(wk, v.x, acc[0]);
        acc[1] = fmaf(wk, v.y, acc[1]);
    }
}

template <int C, int OSTR, int OCOL>
__global__ void k_gatagg(const __half* __restrict__ h,
                         const float* __restrict__ s,
                         const float* __restrict__ t,
                         const float* __restrict__ bias,
                         __half* __restrict__ outh) {
    constexpr int CPL = C / 32;
    int w = (blockIdx.x * blockDim.x + threadIdx.x) >> 5;
    int lane = threadIdx.x & 31;
    if (w >= NN) return;

    const int beg = g_rowptr[w];
    const int end = g_rowptr[w + 1];
    const float tn = t[w];

    float denom = 0.f;
    float acc[CPL];
    #pragma unroll
    for (int q = 0; q < CPL; q++) acc[q] = 0.f;

    int j0 = beg;
    for (; j0 + 32 <= end; j0 += 32) {
        int sj = g_adj[j0 + lane];
        float e = s[sj] + tn;
        e = (e >= 0.f) ? e : 0.2f * e;
        float wv = __expf(e);
        denom += wv;
        #pragma unroll
        for (int k = 0; k < 32; k++) {
            float wk = __shfl_sync(0xffffffffu, wv, k);
            int   sk = __shfl_sync(0xffffffffu, sj, k);
            gat_accum<C>(h, sk, wk, lane, acc);
        }
    }
    if (j0 < end) {
        int j = j0 + lane;
        float wv = 0.f;
        int sj = 0;
        if (j < end) {
            sj = g_adj[j];
            float e = s[sj] + tn;
            e = (e >= 0.f) ? e : 0.2f * e;
            wv = __expf(e);
        }
        denom += wv;
        int cnt = end - j0;
        for (int k = 0; k < cnt; k++) {
            float wk = __shfl_sync(0xffffffffu, wv, k);
            int   sk = __shfl_sync(0xffffffffu, sj, k);
            gat_accum<C>(h, sk, wk, lane, acc);
        }
    }
    #pragma unroll
    for (int o = 16; o; o >>= 1)
        denom += __shfl_xor_sync(0xffffffffu, denom, o);

    const float inv = 1.f / (denom + 1e-16f);
    if (CPL == 4) {
        __half2 hh[2];
        hh[0] = __floats2half2_rn(
            fmaxf(acc[0] * inv + __ldg(bias + lane * 4 + 0), 0.f),
            fmaxf(acc[1] * inv + __ldg(bias + lane * 4 + 1), 0.f));
        hh[1] = __floats2half2_rn(
            fmaxf(acc[2] * inv + __ldg(bias + lane * 4 + 2), 0.f),
            fmaxf(acc[3] * inv + __ldg(bias + lane * 4 + 3), 0.f));
        *reinterpret_cast<uint2*>(outh + (size_t)w * OSTR + OCOL + lane * 4) =
            *reinterpret_cast<uint2*>(hh);
    } else {
        __half2 hh = __floats2half2_rn(
            fmaxf(acc[0] * inv + __ldg(bias + lane * 2 + 0), 0.f),
            fmaxf(acc[1] * inv + __ldg(bias + lane * 2 + 1), 0.f));
        *reinterpret_cast<__half2*>(outh + (size_t)w * OSTR + OCOL + lane * 2) = hh;
    }
}

// ---------------------------------------------------------------------------
// Fused: gemm2 (f1 fp16 @ Wg2 -> h2 fp16) | rowdots2 (f1 fp16, w~2)
// ---------------------------------------------------------------------------
__global__ void __launch_bounds__(256)
k_sgemm2_rd(const __half* __restrict__ f1, const float* __restrict__ Wg2,
            __half* __restrict__ h2) {
    const int bx = blockIdx.x;
    if (bx < GEMMB) {
        gemm_wmma<128, 64, __half, __half>(f1, 128, Wg2, h2, NN, bx);
    } else {
        const int w = ((bx - GEMMB) * 256 + threadIdx.x) >> 5;
        const int lane = threadIdx.x & 31;
        if (w >= NN) return;
        uint2 raw = *reinterpret_cast<const uint2*>(f1 + (size_t)w * 128 + lane * 4);
        float2 v01 = __half22float2(*reinterpret_cast<__half2*>(&raw.x));
        float2 v23 = __half22float2(*reinterpret_cast<__half2*>(&raw.y));
        float4 ws = *reinterpret_cast<const float4*>(g_w2s + lane * 4);
        float4 wd = *reinterpret_cast<const float4*>(g_w2d + lane * 4);
        float ds = v01.x * ws.x + v01.y * ws.y + v23.x * ws.z + v23.y * ws.w;
        float dt = v01.x * wd.x + v01.y * wd.y + v23.x * wd.z + v23.y * wd.w;
        #pragma unroll
        for (int o = 16; o; o >>= 1) {
            ds += __shfl_xor_sync(0xffffffffu, ds, o);
            dt += __shfl_xor_sync(0xffffffffu, dt, o);
        }
        if (lane == 0) { g_s2[w] = ds; g_t2[w] = dt; }
    }
}

// ---------------------------------------------------------------------------
// U & V as single K=128 fp16 GEMMs over xf16 = [x | f2].
// ---------------------------------------------------------------------------
__global__ void __launch_bounds__(256)
k_uvf(const __half* __restrict__ xf16, const float* __restrict__ Wm1,
      __half* __restrict__ U, __half* __restrict__ V) {
    if (blockIdx.y == 0)
        gemm_wmma<128, 128, __half, __half>(xf16, 128, Wm1, U, NN, blockIdx.x);
    else
        gemm_wmma<128, 128, __half, __half>(xf16, 128, Wm1 + 128 * 128, V,
                                            NN, blockIdx.x);
}

// ---------------------------------------------------------------------------
// Edge MLP with FUSED D-GEMM (R15-proven): block handles 128 edges.
// ---------------------------------------------------------------------------
__global__ void __launch_bounds__(256)
k_edgemlp(const int* __restrict__ ei, const float* __restrict__ ed,
          const float* __restrict__ Wd, const float* __restrict__ b1,
          const __half* __restrict__ U, const __half* __restrict__ V,
          const float* __restrict__ Wm2, const float* __restrict__ b2,
          float* __restrict__ out) {
    extern __shared__ unsigned char sm[];
    __half* sB = reinterpret_cast<__half*>(sm);                    // 16 x 128
    __half* sA = reinterpret_cast<__half*>(sm + 4096);             // 128 x 16
    __half* sD = reinterpret_cast<__half*>(sm + 8192);             // 128 x 128
    float*  sC = reinterpret_cast<float*>(sm + 8192 + 32768);      // 8 x 256

    const int tid  = threadIdx.x;
    const int lane = tid & 31;
    const int wid  = tid >> 5;
    const int wm   = wid >> 2, wn = wid & 3;
    const int e0   = blockIdx.x * 128;

    for (int i = tid; i < 16 * 128; i += 256)
        sB[i] = __float2half(Wd[i]);
    for (int i = tid; i < 128 * 8; i += 256) {
        int r = i >> 3, cp = i & 7;
        float2 f = *reinterpret_cast<const float2*>(
            ed + (size_t)(e0 + r) * 16 + cp * 2);
        reinterpret_cast<__half2*>(sA)[i] = __floats2half2_rn(f.x, f.y);
    }
    __syncthreads();

    wmma::fragment<wmma::accumulator, 16, 16, 16, float> acc[4][2];
    wmma::fragment<wmma::matrix_b, 16, 16, 16, __half, wmma::row_major> bf[2];
    #pragma unroll
    for (int j = 0; j < 2; j++)
        wmma::load_matrix_sync(bf[j], sB + wn * 32 + j * 16, 128);
    #pragma unroll
    for (int i = 0; i < 4; i++) {
        wmma::fragment<wmma::matrix_a, 16, 16, 16, __half, wmma::row_major> af;
        wmma::load_matrix_sync(af, sA + (wm * 64 + i * 16) * 16, 16);
        #pragma unroll
        for (int j = 0; j < 2; j++) {
            wmma::fill_fragment(acc[i][j], 0.f);
            wmma::mma_sync(acc[i][j], af, bf[j], acc[i][j]);
        }
    }

    float* scw = sC + wid * 256;
    const int r  = lane >> 1;
    const int c0 = (lane & 1) * 8;
    #pragma unroll
    for (int i = 0; i < 4; i++)
        #pragma unroll
        for (int j = 0; j < 2; j++) {
            wmma::store_matrix_sync(scw, acc[i][j], 16, wmma::mem_row_major);
            __syncwarp();
            float4 p0 = *reinterpret_cast<float4*>(scw + r * 16 + c0);
            float4 p1 = *reinterpret_cast<float4*>(scw + r * 16 + c0 + 4);
            const int lrow = wm * 64 + i * 16 + r;
            const int col  = wn * 32 + j * 16 + c0;
            float4 b0  = *reinterpret_cast<const float4*>(b1 + col);
            float4 b1v = *reinterpret_cast<const float4*>(b1 + col + 4);
            p0.x += b0.x;  p0.y += b0.y;  p0.z += b0.z;  p0.w += b0.w;
            p1.x += b1v.x; p1.y += b1v.y; p1.z += b1v.z; p1.w += b1v.w;
            __half2 h[4];
            h[0] = __floats2half2_rn(p0.x, p0.y);
            h[1] = __floats2half2_rn(p0.z, p0.w);
            h[2] = __floats2half2_rn(p1.x, p1.y);
            h[3] = __floats2half2_rn(p1.z, p1.w);
            *reinterpret_cast<uint4*>(sD + lrow * 128 + col) =
                *reinterpret_cast<uint4*>(h);
            __syncwarp();
        }
    __syncthreads();

    float4 w2r = *reinterpret_cast<const float4*>(Wm2 + lane * 4);
    const float b2v = __ldg(b2);
    const __half2 z2 = __floats2half2_rn(0.f, 0.f);

    #pragma unroll 2
    for (int q = 0; q < 16; q++) {
        const int le = wid * 16 + q;
        const int e  = e0 + le;
        int2 rc = *reinterpret_cast<const int2*>(ei + 2 * e);

        uint2 ur = *reinterpret_cast<const uint2*>(U + (size_t)rc.x * 128 + lane * 4);
        uint2 vr = *reinterpret_cast<const uint2*>(V + (size_t)rc.y * 128 + lane * 4);
        uint2 dr = *reinterpret_cast<const uint2*>(sD + le * 128 + lane * 4);

        __half2 u0 = *reinterpret_cast<__half2*>(&ur.x);
        __half2 u1 = *reinterpret_cast<__half2*>(&ur.y);
        __half2 v0 = *reinterpret_cast<__half2*>(&vr.x);
        __half2 v1 = *reinterpret_cast<__half2*>(&vr.y);
        __half2 d0 = *reinterpret_cast<__half2*>(&dr.x);
        __half2 d1 = *reinterpret_cast<__half2*>(&dr.y);

        __half2 s0 = __hmax2(__hadd2(__hadd2(u0, v0), d0), z2);
        __half2 s1 = __hmax2(__hadd2(__hadd2(u1, v1), d1), z2);

        float2 f0 = __half22float2(s0);
        float2 f1 = __half22float2(s1);
        float p = f0.x * w2r.x + f0.y * w2r.y + f1.x * w2r.z + f1.y * w2r.w;
        #pragma unroll
        for (int o = 16; o; o >>= 1)
            p += __shfl_xor_sync(0xffffffffu, p, o);

        if (lane == 0)
            out[e] = 1.f / (1.f + __expf(-(p + b2v)));
    }
}

// ---------------------------------------------------------------------------
extern "C" void kernel_launch(void* const* d_in, const int* in_sizes, int n_in,
                              void* d_out, int out_size) {
    const float* x    = (const float*)d_in[0];
    const int*   ei   = (const int*)  d_in[1];
    const float* ed   = (const float*)d_in[2];
    const float* Wg1  = (const float*)d_in[3];
    const float* a1s  = (const float*)d_in[4];
    const float* a1d  = (const float*)d_in[5];
    const float* bg1  = (const float*)d_in[6];
    const float* Wg2  = (const float*)d_in[7];
    const float* a2s  = (const float*)d_in[8];
    const float* a2d  = (const float*)d_in[9];
    const float* bg2  = (const float*)d_in[10];
    const float* Wm1  = (const float*)d_in[11];
    const float* bm1  = (const float*)d_in[12];
    const float* Wm2  = (const float*)d_in[13];
    const float* bm2  = (const float*)d_in[14];
    float* out = (float*)d_out;

    __half *h1, *f1, *h2, *xf16, *U, *V;
    float *s1, *t1, *s2, *t2;
    int* degp;
    cudaGetSymbolAddress((void**)&h1, g_h1);
    cudaGetSymbolAddress((void**)&f1, g_f1);
    cudaGetSymbolAddress((void**)&h2, g_h2);
    cudaGetSymbolAddress((void**)&xf16, g_xf16);
    cudaGetSymbolAddress((void**)&U,  g_U);
    cudaGetSymbolAddress((void**)&V,  g_V);
    cudaGetSymbolAddress((void**)&s1, g_s1);
    cudaGetSymbolAddress((void**)&t1, g_t1);
    cudaGetSymbolAddress((void**)&s2, g_s2);
    cudaGetSymbolAddress((void**)&t2, g_t2);
    cudaGetSymbolAddress((void**)&degp, g_deg);

    cudaMemsetAsync(degp, 0, NN * sizeof(int));

    // gemm1 | x->xf16 | hist
    k_pre<<<GEMMB + COPYB + HISTB, 256, GEMM_SMEM>>>(x, ei, Wg1, h1, xf16);
    // scan (+self loops) + w~2
    k_scan<<<1, 1024>>>(Wg2, a2s, a2d);
    // fill | rowdots1
    k_fill_rd<<<FILLB + WB, 256>>>(ei, a1s, a1d);
    // GAT aggregate 1 -> f1 (fp16, compact)
    k_gatagg<128, 128, 0><<<WB, 256>>>(h1, s1, t1, bg1, f1);
    // gemm2 | rowdots2
    k_sgemm2_rd<<<GEMMB + WB, 256, GEMM_SMEM>>>(f1, Wg2, h2);
    // GAT aggregate 2 -> xf16 right half
    k_gatagg<64, 128, 64><<<WB, 256>>>(h2, s2, t2, bg2, xf16);
    // U and V: single K=128 fp16 GEMMs over xf16
    k_uvf<<<dim3(GEMMB, 2), 256, UVF_SMEM>>>(xf16, Wm1, U, V);
    // edge MLP with fused D-GEMM
    k_edgemlp<<<EDGEB, 256, EMLP_SMEM>>>(ei, ed, Wm1 + 256 * 128, bm1,
                                         U, V, Wm2, bm2, out);
}